// round 15
// baseline (speedup 1.0000x reference)
#include <cuda_runtime.h>
#include <cuda_bf16.h>
#include <math.h>
#include <stdint.h>

// ---------------- problem constants ----------------
#define D_MODEL 2048
#define D3      6144
#define DFF     8192
#define TSEQ    1024
#define NBATCH  2
#define NTOK    2048
#define NHEAD   16
#define HD      128

// ---------------- scratch ----------------
static __device__ __align__(128) float g_x1 [NTOK * D_MODEL];
static __device__ __align__(128) float g_S  [NBATCH * NHEAD * TSEQ * TSEQ];   // attention scores

static __device__ __align__(128) __nv_bfloat16 g_xn_h [NTOK * D_MODEL];
static __device__ __align__(128) __nv_bfloat16 g_xn_l [NTOK * D_MODEL];
static __device__ __align__(128) __nv_bfloat16 g_qkv_h[NTOK * D3];
static __device__ __align__(128) __nv_bfloat16 g_qkv_l[NTOK * D3];
static __device__ __align__(128) __nv_bfloat16 g_att_h[NTOK * D_MODEL];
static __device__ __align__(128) __nv_bfloat16 g_att_l[NTOK * D_MODEL];
static __device__ __align__(128) __nv_bfloat16 g_hh   [NTOK * DFF];
static __device__ __align__(128) __nv_bfloat16 g_hl   [NTOK * DFF];

static __device__ __align__(128) __nv_bfloat16 g_wqkv_h [D3  * D_MODEL];
static __device__ __align__(128) __nv_bfloat16 g_wqkv_l [D3  * D_MODEL];
static __device__ __align__(128) __nv_bfloat16 g_wproj_h[D_MODEL * D_MODEL];
static __device__ __align__(128) __nv_bfloat16 g_wproj_l[D_MODEL * D_MODEL];
static __device__ __align__(128) __nv_bfloat16 g_wfc_h  [DFF * D_MODEL];
static __device__ __align__(128) __nv_bfloat16 g_wfc_l  [DFF * D_MODEL];
static __device__ __align__(128) __nv_bfloat16 g_wmp_h  [D_MODEL * DFF];
static __device__ __align__(128) __nv_bfloat16 g_wmp_l  [D_MODEL * DFF];

// ---------------- PWL tables ----------------
static __device__ float g_gx[512], g_gy[512], g_gs[512];
static __device__ float g_ex[512], g_ey[512], g_es[512];
static __device__ float g_ix[512], g_iy[512], g_is[512];
static __device__ float g_rx[512], g_ry[512], g_rs[512];

__global__ void init_tables_kernel()
{
    int i = threadIdx.x;
    {
        double t = -10.0 + 20.0 * (double)i / 511.0;
        float x = (float)t;
        g_gx[i] = x;
        float inner = x + 0.044715f * x * x * x;
        double y = 0.5 * (double)x * (1.0 + tanh(0.7978845608028653559 * (double)inner));
        g_gy[i] = (float)y;
    }
    {
        double t = -30.0 + 30.0 * (double)i / 511.0;
        float x = (float)t;
        g_ex[i] = x;
        g_ey[i] = (float)exp((double)x);
    }
    {
        double lg = -3.0 + (log10(4096.0) + 3.0) * (double)i / 511.0;
        float x = (float)pow(10.0, lg);
        g_ix[i] = x;
        g_iy[i] = 1.0f / x;
    }
    {
        double lg = -6.0 + 8.0 * (double)i / 511.0;
        float x = (float)pow(10.0, lg);
        g_rx[i] = x;
        g_ry[i] = 1.0f / sqrtf(x);
    }
    __syncthreads();
    if (i < 511) {
        g_gs[i] = (g_gy[i + 1] - g_gy[i]) / (g_gx[i + 1] - g_gx[i]);
        g_es[i] = (g_ey[i + 1] - g_ey[i]) / (g_ex[i + 1] - g_ex[i]);
        g_is[i] = (g_iy[i + 1] - g_iy[i]) / (g_ix[i + 1] - g_ix[i]);
        g_rs[i] = (g_ry[i + 1] - g_ry[i]) / (g_rx[i + 1] - g_rx[i]);
    }
}

// ---------------- interp helpers ----------------
__device__ __forceinline__ float pwl_seg(float x, const float* xp, const float* fp,
                                         const float* sl, int i)
{
    i = min(max(i, 0), 510);
    while (i > 0 && x < xp[i]) --i;
    while (i < 510 && x >= xp[i + 1]) ++i;
    return fp[i] + (x - xp[i]) * sl[i];
}
__device__ __forceinline__ float pwl_gelu_f(float x)
{
    if (x <= g_gx[0])   return g_gy[0];
    if (x >= g_gx[511]) return g_gy[511];
    return pwl_seg(x, g_gx, g_gy, g_gs, (int)((x + 10.0f) * (511.0f / 20.0f)));
}
__device__ __forceinline__ float pwl_exp_f(float x)
{
    if (x <= g_ex[0])   return g_ey[0];
    if (x >= g_ex[511]) return g_ey[511];
    return pwl_seg(x, g_ex, g_ey, g_es, (int)((x + 30.0f) * (511.0f / 30.0f)));
}
__device__ __forceinline__ float pwl_inv_f(float x)
{
    if (x <= g_ix[0])   return g_iy[0];
    if (x >= g_ix[511]) return g_iy[511];
    int i = (int)((log2f(x) + 9.965784284662087f) * 23.263455f);
    return pwl_seg(x, g_ix, g_iy, g_is, i);
}
__device__ __forceinline__ float pwl_rsqrt_f(float x)
{
    if (x <= g_rx[0])   return g_ry[0];
    if (x >= g_rx[511]) return g_ry[511];
    int i = (int)((log2f(x) + 19.931568569324174f) * 19.228312f);
    return pwl_seg(x, g_rx, g_ry, g_rs, i);
}

// ---------------- mma / async helpers ----------------
__device__ __forceinline__ uint32_t smem_u32(const void* p)
{
    uint32_t a;
    asm("{ .reg .u64 t; cvta.to.shared.u64 t, %1; cvt.u32.u64 %0, t; }" : "=r"(a) : "l"(p));
    return a;
}
__device__ __forceinline__ void ldsm_x4(uint32_t* r, uint32_t addr)
{
    asm volatile("ldmatrix.sync.aligned.m8n8.x4.shared.b16 {%0,%1,%2,%3}, [%4];"
                 : "=r"(r[0]), "=r"(r[1]), "=r"(r[2]), "=r"(r[3]) : "r"(addr));
}
__device__ __forceinline__ void ldsm_x4t(uint32_t* r, uint32_t addr)
{
    asm volatile("ldmatrix.sync.aligned.m8n8.x4.trans.shared.b16 {%0,%1,%2,%3}, [%4];"
                 : "=r"(r[0]), "=r"(r[1]), "=r"(r[2]), "=r"(r[3]) : "r"(addr));
}
__device__ __forceinline__ void mma16816(float* c, const uint32_t* a, uint32_t b0, uint32_t b1)
{
    asm volatile(
        "mma.sync.aligned.m16n8k16.row.col.f32.bf16.bf16.f32 "
        "{%0,%1,%2,%3}, {%4,%5,%6,%7}, {%8,%9}, {%0,%1,%2,%3};"
        : "+f"(c[0]), "+f"(c[1]), "+f"(c[2]), "+f"(c[3])
        : "r"(a[0]), "r"(a[1]), "r"(a[2]), "r"(a[3]), "r"(b0), "r"(b1));
}
__device__ __forceinline__ void cpa16(uint32_t dst, const void* src)
{
    asm volatile("cp.async.cg.shared.global [%0], [%1], 16;" :: "r"(dst), "l"(src));
}
#define CPA_COMMIT() asm volatile("cp.async.commit_group;" ::: "memory")
#define CPA_WAIT1()  asm volatile("cp.async.wait_group 1;" ::: "memory")
#define CPA_WAIT0()  asm volatile("cp.async.wait_group 0;" ::: "memory")

union BF2U { __nv_bfloat162 h; uint32_t u; };

__device__ __forceinline__ void dec2(float a, float b, uint32_t& h, uint32_t& l)
{
    __nv_bfloat16 ha = __float2bfloat16(a), hb = __float2bfloat16(b);
    BF2U H, L;
    H.h = __halves2bfloat162(ha, hb);
    L.h = __halves2bfloat162(__float2bfloat16(a - __bfloat162float(ha)),
                             __float2bfloat16(b - __bfloat162float(hb)));
    h = H.u; l = L.u;
}

// ---------------- weight prep ----------------
__global__ void __launch_bounds__(256) prep_w_kernel(const float* __restrict__ W,
                                                     __nv_bfloat16* __restrict__ hi,
                                                     __nv_bfloat16* __restrict__ lo,
                                                     int K, int N)
{
    __shared__ float ts[32][33];
    int nb = blockIdx.x * 32, kb = blockIdx.y * 32;
    int tx = threadIdx.x & 31, ty = threadIdx.x >> 5;
#pragma unroll
    for (int j = 0; j < 4; j++)
        ts[ty + 8 * j][tx] = W[(size_t)(kb + ty + 8 * j) * N + nb + tx];
    __syncthreads();
#pragma unroll
    for (int j = 0; j < 4; j++) {
        int n_local = ty + 8 * j;
        float v = ts[tx][n_local];
        __nv_bfloat16 h = __float2bfloat16(v);
        __nv_bfloat16 l = __float2bfloat16(v - __bfloat162float(h));
        size_t o = (size_t)(nb + n_local) * K + kb + tx;
        hi[o] = h;
        lo[o] = l;
    }
}

// ---------------- layernorm ----------------
__global__ void __launch_bounds__(256) ln_kernel(const float* __restrict__ x,
                                                 const float* __restrict__ w,
                                                 const float* __restrict__ b,
                                                 __nv_bfloat16* __restrict__ oh,
                                                 __nv_bfloat16* __restrict__ ol)
{
    __shared__ float red[32];
    int row = blockIdx.x, tid = threadIdx.x;
    const float* xr = x + (size_t)row * D_MODEL;
    int base = tid * 8;
    float4 u0 = *(const float4*)(xr + base);
    float4 u1 = *(const float4*)(xr + base + 4);
    float v[8] = {u0.x, u0.y, u0.z, u0.w, u1.x, u1.y, u1.z, u1.w};

    float s = 0.f;
#pragma unroll
    for (int i = 0; i < 8; i++) s += v[i];
#pragma unroll
    for (int o = 16; o; o >>= 1) s += __shfl_xor_sync(0xffffffffu, s, o);
    int lane = tid & 31, wid = tid >> 5;
    if (lane == 0) red[wid] = s;
    __syncthreads();
    if (tid == 0) {
        float t = 0.f;
#pragma unroll
        for (int i = 0; i < 8; i++) t += red[i];
        red[16] = t * (1.0f / 2048.0f);
    }
    __syncthreads();
    float mu = red[16];

    float sq = 0.f;
#pragma unroll
    for (int i = 0; i < 8; i++) { float d = v[i] - mu; sq += d * d; }
#pragma unroll
    for (int o = 16; o; o >>= 1) sq += __shfl_xor_sync(0xffffffffu, sq, o);
    if (lane == 0) red[wid] = sq;
    __syncthreads();
    if (tid == 0) {
        float t = 0.f;
#pragma unroll
        for (int i = 0; i < 8; i++) t += red[i];
        red[17] = pwl_rsqrt_f(t * (1.0f / 2048.0f) + 1e-5f);
    }
    __syncthreads();
    float inv_std = red[17];

    float4 w0 = *(const float4*)(w + base);
    float4 w1 = *(const float4*)(w + base + 4);
    float4 b0 = *(const float4*)(b + base);
    float4 b1 = *(const float4*)(b + base + 4);
    float wv[8] = {w0.x, w0.y, w0.z, w0.w, w1.x, w1.y, w1.z, w1.w};
    float bv[8] = {b0.x, b0.y, b0.z, b0.w, b1.x, b1.y, b1.z, b1.w};
    float r[8];
#pragma unroll
    for (int i = 0; i < 8; i++) r[i] = (v[i] - mu) * inv_std * wv[i] + bv[i];

    uint32_t hw[4], lw[4];
#pragma unroll
    for (int i = 0; i < 4; i++) dec2(r[i * 2], r[i * 2 + 1], hw[i], lw[i]);
    size_t o = (size_t)row * D_MODEL + base;
    *(uint4*)(oh + o) = make_uint4(hw[0], hw[1], hw[2], hw[3]);
    *(uint4*)(ol + o) = make_uint4(lw[0], lw[1], lw[2], lw[3]);
}

// ---------------- mma.sync bf16x3 GEMM: 128 thr/CTA, warp 64x64, 2-stage cp.async ----------------
#define SSTR 40
#define GTSZ (128 * SSTR * 2)           // 10240 bytes per tile
#define GBUF (4 * GTSZ)                 // Ah, Al, Bh, Bl
#define GEMM_SMEM (2 * GBUF)            // 81920

template <int EPI>
__global__ void __launch_bounds__(128, 2) gemm_mma_kernel(const __nv_bfloat16* __restrict__ Ah_,
                                                          const __nv_bfloat16* __restrict__ Al_,
                                                          const __nv_bfloat16* __restrict__ Bh_,
                                                          const __nv_bfloat16* __restrict__ Bl_,
                                                          const float* __restrict__ bias,
                                                          const float* __restrict__ R,
                                                          float* __restrict__ Cf,
                                                          __nv_bfloat16* __restrict__ Ch,
                                                          __nv_bfloat16* __restrict__ Cl,
                                                          int N, int K)
{
    extern __shared__ char smg[];
    int tid = threadIdx.x;
    int lane = tid & 31, wid = tid >> 5;        // 4 warps
    int wm = wid >> 1, wn = wid & 1;            // 2x2, warp tile 64x64
    int bm = blockIdx.y * 128, bn = blockIdx.x * 128;

    uint32_t u0 = smem_u32(smg);

    uint32_t offA[4], offB[4];
#pragma unroll
    for (int mt = 0; mt < 4; mt++) {
        int row = wm * 64 + mt * 16 + (lane & 15);
        int col = (lane >> 4) << 3;
        offA[mt] = (uint32_t)(row * SSTR + col) * 2;
    }
#pragma unroll
    for (int ntp = 0; ntp < 4; ntp++) {
        int n = wn * 64 + ntp * 16 + ((lane >> 4) << 3) + (lane & 7);
        int k = ((lane >> 3) & 1) << 3;
        offB[ntp] = (uint32_t)(n * SSTR + k) * 2;
    }

    float acc[4][8][4];
#pragma unroll
    for (int mt = 0; mt < 4; mt++)
#pragma unroll
        for (int nt = 0; nt < 8; nt++)
#pragma unroll
            for (int q = 0; q < 4; q++) acc[mt][nt][q] = 0.f;

    // loader: one row per thread, 4x16B per tensor per chunk
    const char* pAh = (const char*)(Ah_ + (size_t)(bm + tid) * K);
    const char* pAl = (const char*)(Al_ + (size_t)(bm + tid) * K);
    const char* pBh = (const char*)(Bh_ + (size_t)(bn + tid) * K);
    const char* pBl = (const char*)(Bl_ + (size_t)(bn + tid) * K);
    uint32_t drow = (uint32_t)(tid * SSTR) * 2;

#define LOAD_CHUNK(ch, buf) do {                                            \
    uint32_t sb = u0 + (buf) * GBUF + drow;                                 \
    size_t so = (size_t)(ch) * 64;                                          \
    _Pragma("unroll")                                                       \
    for (int j = 0; j < 4; j++) {                                           \
        uint32_t sg = (uint32_t)j * 16;                                     \
        cpa16(sb + 0 * GTSZ + sg, pAh + so + sg);                           \
        cpa16(sb + 1 * GTSZ + sg, pAl + so + sg);                           \
        cpa16(sb + 2 * GTSZ + sg, pBh + so + sg);                           \
        cpa16(sb + 3 * GTSZ + sg, pBl + so + sg);                           \
    } } while (0)

    int nch = K >> 5;
    LOAD_CHUNK(0, 0);
    CPA_COMMIT();

    for (int ch = 0; ch < nch; ch++) {
        int cur = ch & 1;
        if (ch + 1 < nch) {
            LOAD_CHUNK(ch + 1, 1 - cur);
            CPA_COMMIT();
            CPA_WAIT1();
        } else {
            CPA_WAIT0();
        }
        __syncthreads();

        uint32_t uAh = u0 + cur * GBUF;
        uint32_t uAl = uAh + GTSZ;
        uint32_t uBh = uAl + GTSZ;
        uint32_t uBl = uBh + GTSZ;
#pragma unroll
        for (int ks = 0; ks < 2; ks++) {
            uint32_t ko = ks * 32;
            uint32_t ah[4][4], al[4][4], bb[4][4];
#pragma unroll
            for (int mt = 0; mt < 4; mt++) {
                ldsm_x4(ah[mt], uAh + offA[mt] + ko);
                ldsm_x4(al[mt], uAl + offA[mt] + ko);
            }
#pragma unroll
            for (int ntp = 0; ntp < 4; ntp++)
                ldsm_x4(bb[ntp], uBh + offB[ntp] + ko);
#pragma unroll
            for (int mt = 0; mt < 4; mt++)
#pragma unroll
                for (int nt = 0; nt < 8; nt++) {
                    uint32_t b0 = bb[nt >> 1][(nt & 1) * 2];
                    uint32_t b1 = bb[nt >> 1][(nt & 1) * 2 + 1];
                    mma16816(acc[mt][nt], ah[mt], b0, b1);
                    mma16816(acc[mt][nt], al[mt], b0, b1);
                }
#pragma unroll
            for (int ntp = 0; ntp < 4; ntp++)
                ldsm_x4(bb[ntp], uBl + offB[ntp] + ko);
#pragma unroll
            for (int mt = 0; mt < 4; mt++)
#pragma unroll
                for (int nt = 0; nt < 8; nt++) {
                    uint32_t b0 = bb[nt >> 1][(nt & 1) * 2];
                    uint32_t b1 = bb[nt >> 1][(nt & 1) * 2 + 1];
                    mma16816(acc[mt][nt], ah[mt], b0, b1);
                }
        }
        __syncthreads();
    }
#undef LOAD_CHUNK

    // ---- epilogue ----
#pragma unroll
    for (int mt = 0; mt < 4; mt++) {
        int row0 = bm + wm * 64 + mt * 16 + (lane >> 2);
#pragma unroll
        for (int nt = 0; nt < 8; nt++) {
            int col = bn + wn * 64 + nt * 8 + (lane & 3) * 2;
            float2 bv = *(const float2*)(bias + col);
            float v0 = acc[mt][nt][0] + bv.x;
            float v1 = acc[mt][nt][1] + bv.y;
            float v2 = acc[mt][nt][2] + bv.x;
            float v3 = acc[mt][nt][3] + bv.y;
            if (EPI == 1) {
                v0 = pwl_gelu_f(v0); v1 = pwl_gelu_f(v1);
                v2 = pwl_gelu_f(v2); v3 = pwl_gelu_f(v3);
            }
            if (EPI == 2) {
                float2 r0 = *(const float2*)(R + (size_t)row0 * N + col);
                float2 r1 = *(const float2*)(R + (size_t)(row0 + 8) * N + col);
                v0 += r0.x; v1 += r0.y; v2 += r1.x; v3 += r1.y;
                *(float2*)(Cf + (size_t)row0 * N + col)       = make_float2(v0, v1);
                *(float2*)(Cf + (size_t)(row0 + 8) * N + col) = make_float2(v2, v3);
            } else {
                uint32_t h0, l0, h1, l1;
                dec2(v0, v1, h0, l0);
                dec2(v2, v3, h1, l1);
                *(uint32_t*)(Ch + (size_t)row0 * N + col)       = h0;
                *(uint32_t*)(Cl + (size_t)row0 * N + col)       = l0;
                *(uint32_t*)(Ch + (size_t)(row0 + 8) * N + col) = h1;
                *(uint32_t*)(Cl + (size_t)(row0 + 8) * N + col) = l1;
            }
        }
    }
}

// ---------------- attention: S-scratch two-pass, trans-ldsm V (R12 version) ----------------
#define QSTR 136
#define VSTR 136
#define ESTR 72
#define A_QH   0
#define A_QL   (A_QH + 64 * QSTR * 2)
#define A_KVH  (A_QL + 64 * QSTR * 2)
#define A_KVL  (A_KVH + 64 * QSTR * 2)
#define A_EH   (A_KVL + 64 * QSTR * 2)
#define A_EL   (A_EH + 64 * ESTR * 2)
#define A_RED  (A_EL + 64 * ESTR * 2)
#define ATT_SMEM (A_RED + 384 * 4)

__global__ void __launch_bounds__(256, 2) attn_mma_kernel(const __nv_bfloat16* __restrict__ qkvh,
                                                          const __nv_bfloat16* __restrict__ qkvl,
                                                          float* __restrict__ Sbuf,
                                                          __nv_bfloat16* __restrict__ atth,
                                                          __nv_bfloat16* __restrict__ attl)
{
    extern __shared__ char sma[];
    float* sRed  = (float*)(sma + A_RED);
    float* sTmp  = sRed;
    float* sFin  = sRed + 128;

    int tid = threadIdx.x;
    int lane = tid & 31, wid = tid >> 5;
    int wm = wid & 3, wn = wid >> 2;
    int qt = (int)(gridDim.x - 1 - blockIdx.x);
    int h = blockIdx.y, bb = blockIdx.z;
    int qbase = qt * 64;
    const float scale = 0.08838834764831845f;

    uint32_t u0 = smem_u32(sma);
    uint32_t uQh = u0 + A_QH, uQl = u0 + A_QL;
    uint32_t uKh = u0 + A_KVH, uKl = u0 + A_KVL;
    uint32_t uVh = u0 + A_KVH, uVl = u0 + A_KVL;
    uint32_t uEh = u0 + A_EH, uEl = u0 + A_EL;

    const __nv_bfloat16* qph = qkvh + (size_t)(bb * TSEQ + qbase) * D3 + h * HD;
    const __nv_bfloat16* qpl = qkvl + (size_t)(bb * TSEQ + qbase) * D3 + h * HD;
    const __nv_bfloat16* kph = qkvh + (size_t)(bb * TSEQ) * D3 + D_MODEL + h * HD;
    const __nv_bfloat16* kpl = qkvl + (size_t)(bb * TSEQ) * D3 + D_MODEL + h * HD;
    const __nv_bfloat16* vph = qkvh + (size_t)(bb * TSEQ) * D3 + 2 * D_MODEL + h * HD;
    const __nv_bfloat16* vpl = qkvl + (size_t)(bb * TSEQ) * D3 + 2 * D_MODEL + h * HD;

    float* Srow = Sbuf + ((size_t)(bb * NHEAD + h) * TSEQ + qbase) * TSEQ;

    int lrow = tid >> 2, lcb = (tid & 3) * 32;
    uint32_t sQrow = (uint32_t)(lrow * QSTR + lcb) * 2;

#pragma unroll
    for (int j = 0; j < 4; j++) {
        *(uint4*)(sma + A_QH + sQrow + j * 16) =
            *(const uint4*)(qph + (size_t)lrow * D3 + lcb + j * 8);
        *(uint4*)(sma + A_QL + sQrow + j * 16) =
            *(const uint4*)(qpl + (size_t)lrow * D3 + lcb + j * 8);
    }

    uint32_t offQA = (uint32_t)((wm * 16 + (lane & 15)) * QSTR + ((lane >> 4) << 3)) * 2;
    uint32_t offKB[2];
#pragma unroll
    for (int ntp = 0; ntp < 2; ntp++) {
        int n = wn * 32 + ntp * 16 + ((lane >> 4) << 3) + (lane & 7);
        offKB[ntp] = (uint32_t)(n * QSTR + (((lane >> 3) & 1) << 3)) * 2;
    }
    uint32_t offEA = (uint32_t)((wm * 16 + (lane & 15)) * ESTR + ((lane >> 4) << 3)) * 2;
    uint32_t offVT[4];
    {
        int vr = (lane & 7) + (((lane >> 3) & 1) << 3);
        int vc = ((lane >> 4) << 3);
#pragma unroll
        for (int g = 0; g < 4; g++)
            offVT[g] = (uint32_t)(vr * VSTR + wn * 64 + g * 16 + vc) * 2;
    }

    int nkt = qt + 1;
    int fr = lane >> 2;
    int grow0 = qbase + wm * 16 + fr;

    // ---- pass 1 ----
    float mx0 = -INFINITY, mx1 = -INFINITY;
    for (int kb = 0; kb < nkt; kb++) {
        __syncthreads();
#pragma unroll
        for (int j = 0; j < 4; j++) {
            *(uint4*)(sma + A_KVH + sQrow + j * 16) =
                *(const uint4*)(kph + (size_t)(kb * 64 + lrow) * D3 + lcb + j * 8);
            *(uint4*)(sma + A_KVL + sQrow + j * 16) =
                *(const uint4*)(kpl + (size_t)(kb * 64 + lrow) * D3 + lcb + j * 8);
        }
        __syncthreads();

        float s[4][4];
#pragma unroll
        for (int nt = 0; nt < 4; nt++)
#pragma unroll
            for (int q = 0; q < 4; q++) s[nt][q] = 0.f;
#pragma unroll
        for (int ks = 0; ks < 8; ks++) {
            uint32_t ko = ks * 32;
            uint32_t qh[4], ql[4], kh[2][4], kl[2][4];
            ldsm_x4(qh, uQh + offQA + ko);
            ldsm_x4(ql, uQl + offQA + ko);
            ldsm_x4(kh[0], uKh + offKB[0] + ko);
            ldsm_x4(kh[1], uKh + offKB[1] + ko);
            ldsm_x4(kl[0], uKl + offKB[0] + ko);
            ldsm_x4(kl[1], uKl + offKB[1] + ko);
#pragma unroll
            for (int nt = 0; nt < 4; nt++) {
                uint32_t b0 = kh[nt >> 1][(nt & 1) * 2];
                uint32_t b1 = kh[nt >> 1][(nt & 1) * 2 + 1];
                mma16816(s[nt], qh, b0, b1);
                mma16816(s[nt], ql, b0, b1);
                uint32_t c0 = kl[nt >> 1][(nt & 1) * 2];
                uint32_t c1 = kl[nt >> 1][(nt & 1) * 2 + 1];
                mma16816(s[nt], qh, c0, c1);
            }
        }
        bool diag = (kb == qt);
#pragma unroll
        for (int nt = 0; nt < 4; nt++) {
            int colb = wn * 32 + nt * 8 + (lane & 3) * 2;
            int gcol = kb * 64 + colb;
            float v0 = s[nt][0] * scale, v1 = s[nt][1] * scale;
            float v2 = s[nt][2] * scale, v3 = s[nt][3] * scale;
            if (diag) {
                if (gcol     > grow0)     v0 = -INFINITY;
                if (gcol + 1 > grow0)     v1 = -INFINITY;
                if (gcol     > grow0 + 8) v2 = -INFINITY;
                if (gcol + 1 > grow0 + 8) v3 = -INFINITY;
            }
            mx0 = fmaxf(mx0, fmaxf(v0, v1));
            mx1 = fmaxf(mx1, fmaxf(v2, v3));
            int r0 = wm * 16 + fr;
            *(float2*)(Srow + (size_t)r0 * TSEQ + gcol)       = make_float2(v0, v1);
            *(float2*)(Srow + (size_t)(r0 + 8) * TSEQ + gcol) = make_float2(v2, v3);
        }
    }
    mx0 = fmaxf(mx0, __shfl_xor_sync(0xffffffffu, mx0, 1));
    mx0 = fmaxf(mx0, __shfl_xor_sync(0xffffffffu, mx0, 2));
    mx1 = fmaxf(mx1, __shfl_xor_sync(0xffffffffu, mx1, 1));
    mx1 = fmaxf(mx1, __shfl_xor_sync(0xffffffffu, mx1, 2));
    __syncthreads();
    if ((lane & 3) == 0) {
        sTmp[wn * 64 + wm * 16 + fr]     = mx0;
        sTmp[wn * 64 + wm * 16 + fr + 8] = mx1;
    }
    __syncthreads();
    if (tid < 64) sFin[tid] = fmaxf(sTmp[tid], sTmp[64 + tid]);
    __syncthreads();
    float m0 = sFin[wm * 16 + fr];
    float m1 = sFin[wm * 16 + fr + 8];

    // ---- pass 2 ----
    float o[8][4];
#pragma unroll
    for (int nt = 0; nt < 8; nt++)
#pragma unroll
        for (int q = 0; q < 4; q++) o[nt][q] = 0.f;
    float sum0 = 0.f, sum1 = 0.f;

    for (int kb = 0; kb < nkt; kb++) {
        __syncthreads();
#pragma unroll
        for (int j = 0; j < 4; j++) {
            *(uint4*)(sma + A_KVH + sQrow + j * 16) =
                *(const uint4*)(vph + (size_t)(kb * 64 + lrow) * D3 + lcb + j * 8);
            *(uint4*)(sma + A_KVL + sQrow + j * 16) =
                *(const uint4*)(vpl + (size_t)(kb * 64 + lrow) * D3 + lcb + j * 8);
        }
#pragma unroll
        for (int nt = 0; nt < 4; nt++) {
            int colb = wn * 32 + nt * 8 + (lane & 3) * 2;
            int gcol = kb * 64 + colb;
            int r0 = wm * 16 + fr;
            float2 a = *(const float2*)(Srow + (size_t)r0 * TSEQ + gcol);
            float2 b = *(const float2*)(Srow + (size_t)(r0 + 8) * TSEQ + gcol);
            float z0 = fminf(fmaxf(a.x - m0, -30.0f), 0.0f);
            float z1 = fminf(fmaxf(a.y - m0, -30.0f), 0.0f);
            float z2 = fminf(fmaxf(b.x - m1, -30.0f), 0.0f);
            float z3 = fminf(fmaxf(b.y - m1, -30.0f), 0.0f);
            float e0 = pwl_exp_f(z0), e1 = pwl_exp_f(z1);
            float e2 = pwl_exp_f(z2), e3 = pwl_exp_f(z3);
            sum0 += e0 + e1;
            sum1 += e2 + e3;
            uint32_t h0, l0, h1, l1;
            dec2(e0, e1, h0, l0);
            dec2(e2, e3, h1, l1);
            *(uint32_t*)(sma + A_EH + (r0 * ESTR + colb) * 2)       = h0;
            *(uint32_t*)(sma + A_EL + (r0 * ESTR + colb) * 2)       = l0;
            *(uint32_t*)(sma + A_EH + ((r0 + 8) * ESTR + colb) * 2) = h1;
            *(uint32_t*)(sma + A_EL + ((r0 + 8) * ESTR + colb) * 2) = l1;
        }
        __syncthreads();

#pragma unroll
        for (int ks = 0; ks < 4; ks++) {
            uint32_t ko = ks * 32;
            uint32_t vko = (uint32_t)(ks * 16 * VSTR) * 2;
            uint32_t eh[4], el[4], vh[4][4], vl[4][4];
            ldsm_x4(eh, uEh + offEA + ko);
            ldsm_x4(el, uEl + offEA + ko);
#pragma unroll
            for (int g = 0; g < 4; g++) {
                ldsm_x4t(vh[g], uVh + offVT[g] + vko);
                ldsm_x4t(vl[g], uVl + offVT[g] + vko);
            }
#pragma unroll
            for (int nt = 0; nt < 8; nt++) {
                uint32_t b0 = vh[nt >> 1][(nt & 1) * 2];
                uint32_t b1 = vh[nt >> 1][(nt & 1) * 2 + 1];
                mma16816(o[nt], eh, b0, b1);
                mma16816(o[nt], el, b0, b1);
                uint32_t c0 = vl[nt >> 1][(nt & 1) * 2];
                uint32_t c1 = vl[nt >> 1][(nt & 1) * 2 + 1];
                mma16816(o[nt], eh, c0, c1);
            }
        }
    }

    sum0 += __shfl_xor_sync(0xffffffffu, sum0, 1);
    sum0 += __shfl_xor_sync(0xffffffffu, sum0, 2);
    sum1 += __shfl_xor_sync(0xffffffffu, sum1, 1);
    sum1 += __shfl_xor_sync(0xffffffffu, sum1, 2);
    __syncthreads();
    if ((lane & 3) == 0) {
        sTmp[wn * 64 + wm * 16 + fr]     = sum0;
        sTmp[wn * 64 + wm * 16 + fr + 8] = sum1;
    }
    __syncthreads();
    if (tid < 64) sFin[tid] = sTmp[tid] + sTmp[64 + tid];
    __syncthreads();

    float inv0 = pwl_inv_f(sFin[wm * 16 + fr]);
    float inv1 = pwl_inv_f(sFin[wm * 16 + fr + 8]);
    size_t row0 = (size_t)(bb * TSEQ + qbase + wm * 16 + fr);
#pragma unroll
    for (int nt = 0; nt < 8; nt++) {
        int col = h * HD + wn * 64 + nt * 8 + (lane & 3) * 2;
        uint32_t h0, l0, h1, l1;
        dec2(o[nt][0] * inv0, o[nt][1] * inv0, h0, l0);
        dec2(o[nt][2] * inv1, o[nt][3] * inv1, h1, l1);
        *(uint32_t*)(atth + row0 * D_MODEL + col)       = h0;
        *(uint32_t*)(attl + row0 * D_MODEL + col)       = l0;
        *(uint32_t*)(atth + (row0 + 8) * D_MODEL + col) = h1;
        *(uint32_t*)(attl + (row0 + 8) * D_MODEL + col) = l1;
    }
}

// ---------------- host launcher ----------------
extern "C" void kernel_launch(void* const* d_in, const int* in_sizes, int n_in,
                              void* d_out, int out_size)
{
    (void)in_sizes; (void)n_in; (void)out_size;
    const float* x      = (const float*)d_in[0];
    const float* ln1w   = (const float*)d_in[1];
    const float* ln1b   = (const float*)d_in[2];
    const float* ln2w   = (const float*)d_in[3];
    const float* ln2b   = (const float*)d_in[4];
    const float* cattw  = (const float*)d_in[5];
    const float* cattb  = (const float*)d_in[6];
    const float* cprojw = (const float*)d_in[7];
    const float* cprojb = (const float*)d_in[8];
    const float* fcw    = (const float*)d_in[9];
    const float* fcb    = (const float*)d_in[10];
    const float* projw  = (const float*)d_in[11];
    const float* projb  = (const float*)d_in[12];
    float* out = (float*)d_out;

    float *x1b, *sbuf;
    cudaGetSymbolAddress((void**)&x1b, g_x1);
    cudaGetSymbolAddress((void**)&sbuf, g_S);

    __nv_bfloat16 *xnh, *xnl, *qkh, *qkl, *ath, *atl, *hh, *hl;
    cudaGetSymbolAddress((void**)&xnh, g_xn_h);
    cudaGetSymbolAddress((void**)&xnl, g_xn_l);
    cudaGetSymbolAddress((void**)&qkh, g_qkv_h);
    cudaGetSymbolAddress((void**)&qkl, g_qkv_l);
    cudaGetSymbolAddress((void**)&ath, g_att_h);
    cudaGetSymbolAddress((void**)&atl, g_att_l);
    cudaGetSymbolAddress((void**)&hh,  g_hh);
    cudaGetSymbolAddress((void**)&hl,  g_hl);

    __nv_bfloat16 *wqh, *wql, *wph, *wpl, *wfh, *wfl, *wmh, *wml;
    cudaGetSymbolAddress((void**)&wqh, g_wqkv_h);
    cudaGetSymbolAddress((void**)&wql, g_wqkv_l);
    cudaGetSymbolAddress((void**)&wph, g_wproj_h);
    cudaGetSymbolAddress((void**)&wpl, g_wproj_l);
    cudaGetSymbolAddress((void**)&wfh, g_wfc_h);
    cudaGetSymbolAddress((void**)&wfl, g_wfc_l);
    cudaGetSymbolAddress((void**)&wmh, g_wmp_h);
    cudaGetSymbolAddress((void**)&wml, g_wmp_l);

    cudaFuncSetAttribute(attn_mma_kernel, cudaFuncAttributeMaxDynamicSharedMemorySize,
                         ATT_SMEM);
    cudaFuncSetAttribute(gemm_mma_kernel<0>, cudaFuncAttributeMaxDynamicSharedMemorySize,
                         GEMM_SMEM);
    cudaFuncSetAttribute(gemm_mma_kernel<1>, cudaFuncAttributeMaxDynamicSharedMemorySize,
                         GEMM_SMEM);
    cudaFuncSetAttribute(gemm_mma_kernel<2>, cudaFuncAttributeMaxDynamicSharedMemorySize,
                         GEMM_SMEM);

    init_tables_kernel<<<1, 512>>>();

    prep_w_kernel<<<dim3(D3 / 32,      D_MODEL / 32), 256>>>(cattw,  wqh, wql, D_MODEL, D3);
    prep_w_kernel<<<dim3(D_MODEL / 32, D_MODEL / 32), 256>>>(cprojw, wph, wpl, D_MODEL, D_MODEL);
    prep_w_kernel<<<dim3(DFF / 32,     D_MODEL / 32), 256>>>(fcw,    wfh, wfl, D_MODEL, DFF);
    prep_w_kernel<<<dim3(D_MODEL / 32, DFF / 32),     256>>>(projw,  wmh, wml, DFF, D_MODEL);

    // x -> ln1 -> qkv (bf16 hi/lo out)
    ln_kernel<<<NTOK, 256>>>(x, ln1w, ln1b, xnh, xnl);
    gemm_mma_kernel<0><<<dim3(D3 / 128, NTOK / 128), 128, GEMM_SMEM>>>(
        xnh, xnl, wqh, wql, cattb, nullptr, nullptr, qkh, qkl, D3, D_MODEL);

    // attention
    attn_mma_kernel<<<dim3(TSEQ / 64, NHEAD, NBATCH), 256, ATT_SMEM>>>(
        qkh, qkl, sbuf, ath, atl);

    // x1 = x + att @ c_proj + b   (fp32 out)
    gemm_mma_kernel<2><<<dim3(D_MODEL / 128, NTOK / 128), 128, GEMM_SMEM>>>(
        ath, atl, wph, wpl, cprojb, x, x1b, nullptr, nullptr, D_MODEL, D_MODEL);

    // ln2 -> h = gelu(fc)  (bf16 hi/lo out)
    ln_kernel<<<NTOK, 256>>>(x1b, ln2w, ln2b, xnh, xnl);
    gemm_mma_kernel<1><<<dim3(DFF / 128, NTOK / 128), 128, GEMM_SMEM>>>(
        xnh, xnl, wfh, wfl, fcb, nullptr, nullptr, hh, hl, DFF, D_MODEL);

    // out = x1 + h @ proj + b  (fp32 out)
    gemm_mma_kernel<2><<<dim3(D_MODEL / 128, NTOK / 128), 128, GEMM_SMEM>>>(
        hh, hl, wmh, wml, projb, x1b, out, nullptr, nullptr, D_MODEL, DFF);
}

// round 16
// speedup vs baseline: 1.6255x; 1.6255x over previous
#include <cuda_runtime.h>
#include <cuda_fp16.h>
#include <math.h>
#include <stdint.h>

// ---------------- problem constants ----------------
#define D_MODEL 2048
#define D3      6144
#define DFF     8192
#define TSEQ    1024
#define NBATCH  2
#define NTOK    2048
#define NHEAD   16
#define HD      128

// ---------------- scratch ----------------
static __device__ __align__(128) float g_x1 [NTOK * D_MODEL];
static __device__ __align__(128) float g_S  [NBATCH * NHEAD * TSEQ * TSEQ];

// activations: single fp16 except qkv (hi/lo, K/V need the split)
static __device__ __align__(128) __half g_xn  [NTOK * D_MODEL];
static __device__ __align__(128) __half g_qkv_h[NTOK * D3];
static __device__ __align__(128) __half g_qkv_l[NTOK * D3];
static __device__ __align__(128) __half g_att [NTOK * D_MODEL];
static __device__ __align__(128) __half g_h   [NTOK * DFF];

// pre-transposed + hi/lo decomposed weights: layout [N][K] fp16
static __device__ __align__(128) __half g_wqkv_h [D3  * D_MODEL];
static __device__ __align__(128) __half g_wqkv_l [D3  * D_MODEL];
static __device__ __align__(128) __half g_wproj_h[D_MODEL * D_MODEL];
static __device__ __align__(128) __half g_wproj_l[D_MODEL * D_MODEL];
static __device__ __align__(128) __half g_wfc_h  [DFF * D_MODEL];
static __device__ __align__(128) __half g_wfc_l  [DFF * D_MODEL];
static __device__ __align__(128) __half g_wmp_h  [D_MODEL * DFF];
static __device__ __align__(128) __half g_wmp_l  [D_MODEL * DFF];

// ---------------- PWL tables ----------------
static __device__ float g_gx[512], g_gy[512], g_gs[512];
static __device__ float g_ex[512], g_ey[512], g_es[512];
static __device__ float g_ix[512], g_iy[512], g_is[512];
static __device__ float g_rx[512], g_ry[512], g_rs[512];

__global__ void init_tables_kernel()
{
    int i = threadIdx.x;
    {
        double t = -10.0 + 20.0 * (double)i / 511.0;
        float x = (float)t;
        g_gx[i] = x;
        float inner = x + 0.044715f * x * x * x;
        double y = 0.5 * (double)x * (1.0 + tanh(0.7978845608028653559 * (double)inner));
        g_gy[i] = (float)y;
    }
    {
        double t = -30.0 + 30.0 * (double)i / 511.0;
        float x = (float)t;
        g_ex[i] = x;
        g_ey[i] = (float)exp((double)x);
    }
    {
        double lg = -3.0 + (log10(4096.0) + 3.0) * (double)i / 511.0;
        float x = (float)pow(10.0, lg);
        g_ix[i] = x;
        g_iy[i] = 1.0f / x;
    }
    {
        double lg = -6.0 + 8.0 * (double)i / 511.0;
        float x = (float)pow(10.0, lg);
        g_rx[i] = x;
        g_ry[i] = 1.0f / sqrtf(x);
    }
    __syncthreads();
    if (i < 511) {
        g_gs[i] = (g_gy[i + 1] - g_gy[i]) / (g_gx[i + 1] - g_gx[i]);
        g_es[i] = (g_ey[i + 1] - g_ey[i]) / (g_ex[i + 1] - g_ex[i]);
        g_is[i] = (g_iy[i + 1] - g_iy[i]) / (g_ix[i + 1] - g_ix[i]);
        g_rs[i] = (g_ry[i + 1] - g_ry[i]) / (g_rx[i + 1] - g_rx[i]);
    }
}

// ---------------- interp helpers ----------------
__device__ __forceinline__ float pwl_seg(float x, const float* xp, const float* fp,
                                         const float* sl, int i)
{
    i = min(max(i, 0), 510);
    while (i > 0 && x < xp[i]) --i;
    while (i < 510 && x >= xp[i + 1]) ++i;
    return fp[i] + (x - xp[i]) * sl[i];
}
__device__ __forceinline__ float pwl_gelu_f(float x)
{
    if (x <= g_gx[0])   return g_gy[0];
    if (x >= g_gx[511]) return g_gy[511];
    return pwl_seg(x, g_gx, g_gy, g_gs, (int)((x + 10.0f) * (511.0f / 20.0f)));
}
__device__ __forceinline__ float pwl_exp_f(float x)
{
    if (x <= g_ex[0])   return g_ey[0];
    if (x >= g_ex[511]) return g_ey[511];
    return pwl_seg(x, g_ex, g_ey, g_es, (int)((x + 30.0f) * (511.0f / 30.0f)));
}
__device__ __forceinline__ float pwl_inv_f(float x)
{
    if (x <= g_ix[0])   return g_iy[0];
    if (x >= g_ix[511]) return g_iy[511];
    int i = (int)((log2f(x) + 9.965784284662087f) * 23.263455f);
    return pwl_seg(x, g_ix, g_iy, g_is, i);
}
__device__ __forceinline__ float pwl_rsqrt_f(float x)
{
    if (x <= g_rx[0])   return g_ry[0];
    if (x >= g_rx[511]) return g_ry[511];
    int i = (int)((log2f(x) + 19.931568569324174f) * 19.228312f);
    return pwl_seg(x, g_rx, g_ry, g_rs, i);
}

// ---------------- mma / async helpers ----------------
__device__ __forceinline__ uint32_t smem_u32(const void* p)
{
    uint32_t a;
    asm("{ .reg .u64 t; cvta.to.shared.u64 t, %1; cvt.u32.u64 %0, t; }" : "=r"(a) : "l"(p));
    return a;
}
__device__ __forceinline__ void ldsm_x4(uint32_t* r, uint32_t addr)
{
    asm volatile("ldmatrix.sync.aligned.m8n8.x4.shared.b16 {%0,%1,%2,%3}, [%4];"
                 : "=r"(r[0]), "=r"(r[1]), "=r"(r[2]), "=r"(r[3]) : "r"(addr));
}
__device__ __forceinline__ void ldsm_x4t(uint32_t* r, uint32_t addr)
{
    asm volatile("ldmatrix.sync.aligned.m8n8.x4.trans.shared.b16 {%0,%1,%2,%3}, [%4];"
                 : "=r"(r[0]), "=r"(r[1]), "=r"(r[2]), "=r"(r[3]) : "r"(addr));
}
__device__ __forceinline__ void mma16816(float* c, const uint32_t* a, uint32_t b0, uint32_t b1)
{
    asm volatile(
        "mma.sync.aligned.m16n8k16.row.col.f32.f16.f16.f32 "
        "{%0,%1,%2,%3}, {%4,%5,%6,%7}, {%8,%9}, {%0,%1,%2,%3};"
        : "+f"(c[0]), "+f"(c[1]), "+f"(c[2]), "+f"(c[3])
        : "r"(a[0]), "r"(a[1]), "r"(a[2]), "r"(a[3]), "r"(b0), "r"(b1));
}
__device__ __forceinline__ void cpa16(uint32_t dst, const void* src)
{
    asm volatile("cp.async.cg.shared.global [%0], [%1], 16;" :: "r"(dst), "l"(src));
}
#define CPA_COMMIT() asm volatile("cp.async.commit_group;" ::: "memory")
#define CPA_WAIT1()  asm volatile("cp.async.wait_group 1;" ::: "memory")
#define CPA_WAIT0()  asm volatile("cp.async.wait_group 0;" ::: "memory")

union H2U { __half2 h; uint32_t u; };

__device__ __forceinline__ uint32_t pack2h(float a, float b)
{
    H2U u;
    u.h = __floats2half2_rn(a, b);
    return u.u;
}
__device__ __forceinline__ void dec2h(float a, float b, uint32_t& h, uint32_t& l)
{
    __half ha = __float2half_rn(a), hb = __float2half_rn(b);
    H2U H, L;
    H.h = __halves2half2(ha, hb);
    L.h = __halves2half2(__float2half_rn(a - __half2float(ha)),
                         __float2half_rn(b - __half2float(hb)));
    h = H.u; l = L.u;
}

// ---------------- weight prep: W[K][N] fp32 -> fp16 hi/lo [N][K] ----------------
__global__ void __launch_bounds__(256) prep_w_kernel(const float* __restrict__ W,
                                                     __half* __restrict__ hi,
                                                     __half* __restrict__ lo,
                                                     int K, int N)
{
    __shared__ float ts[32][33];
    int nb = blockIdx.x * 32, kb = blockIdx.y * 32;
    int tx = threadIdx.x & 31, ty = threadIdx.x >> 5;
#pragma unroll
    for (int j = 0; j < 4; j++)
        ts[ty + 8 * j][tx] = W[(size_t)(kb + ty + 8 * j) * N + nb + tx];
    __syncthreads();
#pragma unroll
    for (int j = 0; j < 4; j++) {
        int n_local = ty + 8 * j;
        float v = ts[tx][n_local];
        __half h = __float2half_rn(v);
        __half l = __float2half_rn(v - __half2float(h));
        size_t o = (size_t)(nb + n_local) * K + kb + tx;
        hi[o] = h;
        lo[o] = l;
    }
}

// ---------------- layernorm: fp32 in -> single fp16 out ----------------
__global__ void __launch_bounds__(256) ln_kernel(const float* __restrict__ x,
                                                 const float* __restrict__ w,
                                                 const float* __restrict__ b,
                                                 __half* __restrict__ oh)
{
    __shared__ float red[32];
    int row = blockIdx.x, tid = threadIdx.x;
    const float* xr = x + (size_t)row * D_MODEL;
    int base = tid * 8;
    float4 u0 = *(const float4*)(xr + base);
    float4 u1 = *(const float4*)(xr + base + 4);
    float v[8] = {u0.x, u0.y, u0.z, u0.w, u1.x, u1.y, u1.z, u1.w};

    float s = 0.f;
#pragma unroll
    for (int i = 0; i < 8; i++) s += v[i];
#pragma unroll
    for (int o = 16; o; o >>= 1) s += __shfl_xor_sync(0xffffffffu, s, o);
    int lane = tid & 31, wid = tid >> 5;
    if (lane == 0) red[wid] = s;
    __syncthreads();
    if (tid == 0) {
        float t = 0.f;
#pragma unroll
        for (int i = 0; i < 8; i++) t += red[i];
        red[16] = t * (1.0f / 2048.0f);
    }
    __syncthreads();
    float mu = red[16];

    float sq = 0.f;
#pragma unroll
    for (int i = 0; i < 8; i++) { float d = v[i] - mu; sq += d * d; }
#pragma unroll
    for (int o = 16; o; o >>= 1) sq += __shfl_xor_sync(0xffffffffu, sq, o);
    if (lane == 0) red[wid] = sq;
    __syncthreads();
    if (tid == 0) {
        float t = 0.f;
#pragma unroll
        for (int i = 0; i < 8; i++) t += red[i];
        red[17] = pwl_rsqrt_f(t * (1.0f / 2048.0f) + 1e-5f);
    }
    __syncthreads();
    float inv_std = red[17];

    float4 w0 = *(const float4*)(w + base);
    float4 w1 = *(const float4*)(w + base + 4);
    float4 b0 = *(const float4*)(b + base);
    float4 b1 = *(const float4*)(b + base + 4);
    float wv[8] = {w0.x, w0.y, w0.z, w0.w, w1.x, w1.y, w1.z, w1.w};
    float bv[8] = {b0.x, b0.y, b0.z, b0.w, b1.x, b1.y, b1.z, b1.w};
    float r[8];
#pragma unroll
    for (int i = 0; i < 8; i++) r[i] = (v[i] - mu) * inv_std * wv[i] + bv[i];

    uint32_t hw[4];
#pragma unroll
    for (int i = 0; i < 4; i++) hw[i] = pack2h(r[i * 2], r[i * 2 + 1]);
    size_t o = (size_t)row * D_MODEL + base;
    *(uint4*)(oh + o) = make_uint4(hw[0], hw[1], hw[2], hw[3]);
}

// ---------------- fp16 GEMM: A single, W hi/lo (2 terms), R12 shape ----------------
#define SSTR 40
#define GTSZ (128 * SSTR * 2)           // 10240 bytes per tile
#define GBUF (3 * GTSZ)                 // A, Bh, Bl
#define GEMM_SMEM (2 * GBUF)            // 61440

template <int EPI>
__global__ void __launch_bounds__(256, 2) gemm_mma_kernel(const __half* __restrict__ A_,
                                                          const __half* __restrict__ Bh_,
                                                          const __half* __restrict__ Bl_,
                                                          const float* __restrict__ bias,
                                                          const float* __restrict__ R,
                                                          float* __restrict__ Cf,
                                                          __half* __restrict__ Ch,
                                                          __half* __restrict__ Cl,
                                                          int N, int K)
{
    extern __shared__ char smg[];
    int tid = threadIdx.x;
    int lane = tid & 31, wid = tid >> 5;
    int wm = wid & 3, wn = wid >> 2;
    int bm = blockIdx.y * 128, bn = blockIdx.x * 128;

    uint32_t u0 = smem_u32(smg);

    uint32_t offA[2], offB[4];
#pragma unroll
    for (int mt = 0; mt < 2; mt++) {
        int row = wm * 32 + mt * 16 + (lane & 15);
        int col = (lane >> 4) << 3;
        offA[mt] = (uint32_t)(row * SSTR + col) * 2;
    }
#pragma unroll
    for (int ntp = 0; ntp < 4; ntp++) {
        int n = wn * 64 + ntp * 16 + ((lane >> 4) << 3) + (lane & 7);
        int k = ((lane >> 3) & 1) << 3;
        offB[ntp] = (uint32_t)(n * SSTR + k) * 2;
    }

    float acc[2][8][4];
#pragma unroll
    for (int mt = 0; mt < 2; mt++)
#pragma unroll
        for (int nt = 0; nt < 8; nt++)
#pragma unroll
            for (int q = 0; q < 4; q++) acc[mt][nt][q] = 0.f;

    int lrow = tid >> 1;
    int lsg  = (tid & 1) * 2;
    const char* pA  = (const char*)(A_  + (size_t)(bm + lrow) * K);
    const char* pBh = (const char*)(Bh_ + (size_t)(bn + lrow) * K);
    const char* pBl = (const char*)(Bl_ + (size_t)(bn + lrow) * K);
    uint32_t drow = (uint32_t)(lrow * SSTR) * 2;

#define LOAD_CHUNK(ch, buf) do {                                            \
    uint32_t sb = u0 + (buf) * GBUF + drow;                                 \
    size_t so = (size_t)(ch) * 64;                                          \
    _Pragma("unroll")                                                       \
    for (int j = 0; j < 2; j++) {                                           \
        uint32_t sg = (uint32_t)(lsg + j) * 16;                             \
        cpa16(sb + 0 * GTSZ + sg, pA  + so + sg);                           \
        cpa16(sb + 1 * GTSZ + sg, pBh + so + sg);                           \
        cpa16(sb + 2 * GTSZ + sg, pBl + so + sg);                           \
    } } while (0)

    int nch = K >> 5;
    LOAD_CHUNK(0, 0);
    CPA_COMMIT();

    for (int ch = 0; ch < nch; ch++) {
        int cur = ch & 1;
        if (ch + 1 < nch) {
            LOAD_CHUNK(ch + 1, 1 - cur);
            CPA_COMMIT();
            CPA_WAIT1();
        } else {
            CPA_WAIT0();
        }
        __syncthreads();

        uint32_t uA  = u0 + cur * GBUF;
        uint32_t uBh = uA + GTSZ;
        uint32_t uBl = uBh + GTSZ;
#pragma unroll
        for (int ks = 0; ks < 2; ks++) {
            uint32_t ko = ks * 32;
            uint32_t ah[2][4], bb[4][4];
#pragma unroll
            for (int mt = 0; mt < 2; mt++)
                ldsm_x4(ah[mt], uA + offA[mt] + ko);
#pragma unroll
            for (int ntp = 0; ntp < 4; ntp++)
                ldsm_x4(bb[ntp], uBh + offB[ntp] + ko);
#pragma unroll
            for (int mt = 0; mt < 2; mt++)
#pragma unroll
                for (int nt = 0; nt < 8; nt++) {
                    uint32_t b0 = bb[nt >> 1][(nt & 1) * 2];
                    uint32_t b1 = bb[nt >> 1][(nt & 1) * 2 + 1];
                    mma16816(acc[mt][nt], ah[mt], b0, b1);
                }
#pragma unroll
            for (int ntp = 0; ntp < 4; ntp++)
                ldsm_x4(bb[ntp], uBl + offB[ntp] + ko);
#pragma unroll
            for (int mt = 0; mt < 2; mt++)
#pragma unroll
                for (int nt = 0; nt < 8; nt++) {
                    uint32_t b0 = bb[nt >> 1][(nt & 1) * 2];
                    uint32_t b1 = bb[nt >> 1][(nt & 1) * 2 + 1];
                    mma16816(acc[mt][nt], ah[mt], b0, b1);
                }
        }
        __syncthreads();
    }
#undef LOAD_CHUNK

    // ---- epilogue ----
#pragma unroll
    for (int mt = 0; mt < 2; mt++) {
        int row0 = bm + wm * 32 + mt * 16 + (lane >> 2);
#pragma unroll
        for (int nt = 0; nt < 8; nt++) {
            int col = bn + wn * 64 + nt * 8 + (lane & 3) * 2;
            float2 bv = *(const float2*)(bias + col);
            float v0 = acc[mt][nt][0] + bv.x;
            float v1 = acc[mt][nt][1] + bv.y;
            float v2 = acc[mt][nt][2] + bv.x;
            float v3 = acc[mt][nt][3] + bv.y;
            if (EPI == 1) {
                v0 = pwl_gelu_f(v0); v1 = pwl_gelu_f(v1);
                v2 = pwl_gelu_f(v2); v3 = pwl_gelu_f(v3);
            }
            if (EPI == 2) {
                float2 r0 = *(const float2*)(R + (size_t)row0 * N + col);
                float2 r1 = *(const float2*)(R + (size_t)(row0 + 8) * N + col);
                v0 += r0.x; v1 += r0.y; v2 += r1.x; v3 += r1.y;
                *(float2*)(Cf + (size_t)row0 * N + col)       = make_float2(v0, v1);
                *(float2*)(Cf + (size_t)(row0 + 8) * N + col) = make_float2(v2, v3);
            } else if (EPI == 0) {
                uint32_t h0, l0, h1, l1;
                dec2h(v0, v1, h0, l0);
                dec2h(v2, v3, h1, l1);
                *(uint32_t*)(Ch + (size_t)row0 * N + col)       = h0;
                *(uint32_t*)(Cl + (size_t)row0 * N + col)       = l0;
                *(uint32_t*)(Ch + (size_t)(row0 + 8) * N + col) = h1;
                *(uint32_t*)(Cl + (size_t)(row0 + 8) * N + col) = l1;
            } else {
                *(uint32_t*)(Ch + (size_t)row0 * N + col)       = pack2h(v0, v1);
                *(uint32_t*)(Ch + (size_t)(row0 + 8) * N + col) = pack2h(v2, v3);
            }
        }
    }
}

// ---------------- attention: fp16, Q single + K hi/lo, E single + V hi/lo ----------------
#define QSTR 136
#define VSTR 136
#define ESTR 72
#define A_Q    0
#define A_KVH  (A_Q + 64 * QSTR * 2)
#define A_KVL  (A_KVH + 64 * QSTR * 2)
#define A_E    (A_KVL + 64 * QSTR * 2)
#define A_RED  (A_E + 64 * ESTR * 2)
#define ATT_SMEM (A_RED + 384 * 4)

__global__ void __launch_bounds__(256, 2) attn_mma_kernel(const __half* __restrict__ qkvh,
                                                          const __half* __restrict__ qkvl,
                                                          float* __restrict__ Sbuf,
                                                          __half* __restrict__ att)
{
    extern __shared__ char sma[];
    float* sRed  = (float*)(sma + A_RED);
    float* sTmp  = sRed;
    float* sFin  = sRed + 128;

    int tid = threadIdx.x;
    int lane = tid & 31, wid = tid >> 5;
    int wm = wid & 3, wn = wid >> 2;
    int qt = (int)(gridDim.x - 1 - blockIdx.x);
    int h = blockIdx.y, bb = blockIdx.z;
    int qbase = qt * 64;
    const float scale = 0.08838834764831845f;

    uint32_t u0 = smem_u32(sma);
    uint32_t uQ = u0 + A_Q;
    uint32_t uKh = u0 + A_KVH, uKl = u0 + A_KVL;
    uint32_t uVh = u0 + A_KVH, uVl = u0 + A_KVL;
    uint32_t uE = u0 + A_E;

    const __half* qph = qkvh + (size_t)(bb * TSEQ + qbase) * D3 + h * HD;
    const __half* kph = qkvh + (size_t)(bb * TSEQ) * D3 + D_MODEL + h * HD;
    const __half* kpl = qkvl + (size_t)(bb * TSEQ) * D3 + D_MODEL + h * HD;
    const __half* vph = qkvh + (size_t)(bb * TSEQ) * D3 + 2 * D_MODEL + h * HD;
    const __half* vpl = qkvl + (size_t)(bb * TSEQ) * D3 + 2 * D_MODEL + h * HD;

    float* Srow = Sbuf + ((size_t)(bb * NHEAD + h) * TSEQ + qbase) * TSEQ;

    int lrow = tid >> 2, lcb = (tid & 3) * 32;
    uint32_t sQrow = (uint32_t)(lrow * QSTR + lcb) * 2;

    // Q single fp16 (hi part only)
#pragma unroll
    for (int j = 0; j < 4; j++)
        *(uint4*)(sma + A_Q + sQrow + j * 16) =
            *(const uint4*)(qph + (size_t)lrow * D3 + lcb + j * 8);

    uint32_t offQA = (uint32_t)((wm * 16 + (lane & 15)) * QSTR + ((lane >> 4) << 3)) * 2;
    uint32_t offKB[2];
#pragma unroll
    for (int ntp = 0; ntp < 2; ntp++) {
        int n = wn * 32 + ntp * 16 + ((lane >> 4) << 3) + (lane & 7);
        offKB[ntp] = (uint32_t)(n * QSTR + (((lane >> 3) & 1) << 3)) * 2;
    }
    uint32_t offEA = (uint32_t)((wm * 16 + (lane & 15)) * ESTR + ((lane >> 4) << 3)) * 2;
    uint32_t offVT[4];
    {
        int vr = (lane & 7) + (((lane >> 3) & 1) << 3);
        int vc = ((lane >> 4) << 3);
#pragma unroll
        for (int g = 0; g < 4; g++)
            offVT[g] = (uint32_t)(vr * VSTR + wn * 64 + g * 16 + vc) * 2;
    }

    int nkt = qt + 1;
    int fr = lane >> 2;
    int grow0 = qbase + wm * 16 + fr;

    // ---- pass 1: S = Q (Kh + Kl)^T ----
    float mx0 = -INFINITY, mx1 = -INFINITY;
    for (int kb = 0; kb < nkt; kb++) {
        __syncthreads();
#pragma unroll
        for (int j = 0; j < 4; j++) {
            *(uint4*)(sma + A_KVH + sQrow + j * 16) =
                *(const uint4*)(kph + (size_t)(kb * 64 + lrow) * D3 + lcb + j * 8);
            *(uint4*)(sma + A_KVL + sQrow + j * 16) =
                *(const uint4*)(kpl + (size_t)(kb * 64 + lrow) * D3 + lcb + j * 8);
        }
        __syncthreads();

        float s[4][4];
#pragma unroll
        for (int nt = 0; nt < 4; nt++)
#pragma unroll
            for (int q = 0; q < 4; q++) s[nt][q] = 0.f;
#pragma unroll
        for (int ks = 0; ks < 8; ks++) {
            uint32_t ko = ks * 32;
            uint32_t qf[4], kh[2][4], kl[2][4];
            ldsm_x4(qf, uQ + offQA + ko);
            ldsm_x4(kh[0], uKh + offKB[0] + ko);
            ldsm_x4(kh[1], uKh + offKB[1] + ko);
            ldsm_x4(kl[0], uKl + offKB[0] + ko);
            ldsm_x4(kl[1], uKl + offKB[1] + ko);
#pragma unroll
            for (int nt = 0; nt < 4; nt++) {
                uint32_t b0 = kh[nt >> 1][(nt & 1) * 2];
                uint32_t b1 = kh[nt >> 1][(nt & 1) * 2 + 1];
                mma16816(s[nt], qf, b0, b1);
                uint32_t c0 = kl[nt >> 1][(nt & 1) * 2];
                uint32_t c1 = kl[nt >> 1][(nt & 1) * 2 + 1];
                mma16816(s[nt], qf, c0, c1);
            }
        }
        bool diag = (kb == qt);
#pragma unroll
        for (int nt = 0; nt < 4; nt++) {
            int colb = wn * 32 + nt * 8 + (lane & 3) * 2;
            int gcol = kb * 64 + colb;
            float v0 = s[nt][0] * scale, v1 = s[nt][1] * scale;
            float v2 = s[nt][2] * scale, v3 = s[nt][3] * scale;
            if (diag) {
                if (gcol     > grow0)     v0 = -INFINITY;
                if (gcol + 1 > grow0)     v1 = -INFINITY;
                if (gcol     > grow0 + 8) v2 = -INFINITY;
                if (gcol + 1 > grow0 + 8) v3 = -INFINITY;
            }
            mx0 = fmaxf(mx0, fmaxf(v0, v1));
            mx1 = fmaxf(mx1, fmaxf(v2, v3));
            int r0 = wm * 16 + fr;
            *(float2*)(Srow + (size_t)r0 * TSEQ + gcol)       = make_float2(v0, v1);
            *(float2*)(Srow + (size_t)(r0 + 8) * TSEQ + gcol) = make_float2(v2, v3);
        }
    }
    mx0 = fmaxf(mx0, __shfl_xor_sync(0xffffffffu, mx0, 1));
    mx0 = fmaxf(mx0, __shfl_xor_sync(0xffffffffu, mx0, 2));
    mx1 = fmaxf(mx1, __shfl_xor_sync(0xffffffffu, mx1, 1));
    mx1 = fmaxf(mx1, __shfl_xor_sync(0xffffffffu, mx1, 2));
    __syncthreads();
    if ((lane & 3) == 0) {
        sTmp[wn * 64 + wm * 16 + fr]     = mx0;
        sTmp[wn * 64 + wm * 16 + fr + 8] = mx1;
    }
    __syncthreads();
    if (tid < 64) sFin[tid] = fmaxf(sTmp[tid], sTmp[64 + tid]);
    __syncthreads();
    float m0 = sFin[wm * 16 + fr];
    float m1 = sFin[wm * 16 + fr + 8];

    // ---- pass 2: E single fp16, o += E (Vh + Vl) ----
    float o[8][4];
#pragma unroll
    for (int nt = 0; nt < 8; nt++)
#pragma unroll
        for (int q = 0; q < 4; q++) o[nt][q] = 0.f;
    float sum0 = 0.f, sum1 = 0.f;

    for (int kb = 0; kb < nkt; kb++) {
        __syncthreads();
#pragma unroll
        for (int j = 0; j < 4; j++) {
            *(uint4*)(sma + A_KVH + sQrow + j * 16) =
                *(const uint4*)(vph + (size_t)(kb * 64 + lrow) * D3 + lcb + j * 8);
            *(uint4*)(sma + A_KVL + sQrow + j * 16) =
                *(const uint4*)(vpl + (size_t)(kb * 64 + lrow) * D3 + lcb + j * 8);
        }
#pragma unroll
        for (int nt = 0; nt < 4; nt++) {
            int colb = wn * 32 + nt * 8 + (lane & 3) * 2;
            int gcol = kb * 64 + colb;
            int r0 = wm * 16 + fr;
            float2 a = *(const float2*)(Srow + (size_t)r0 * TSEQ + gcol);
            float2 b = *(const float2*)(Srow + (size_t)(r0 + 8) * TSEQ + gcol);
            float z0 = fminf(fmaxf(a.x - m0, -30.0f), 0.0f);
            float z1 = fminf(fmaxf(a.y - m0, -30.0f), 0.0f);
            float z2 = fminf(fmaxf(b.x - m1, -30.0f), 0.0f);
            float z3 = fminf(fmaxf(b.y - m1, -30.0f), 0.0f);
            float e0 = pwl_exp_f(z0), e1 = pwl_exp_f(z1);
            float e2 = pwl_exp_f(z2), e3 = pwl_exp_f(z3);
            sum0 += e0 + e1;
            sum1 += e2 + e3;
            *(uint32_t*)(sma + A_E + (r0 * ESTR + colb) * 2)       = pack2h(e0, e1);
            *(uint32_t*)(sma + A_E + ((r0 + 8) * ESTR + colb) * 2) = pack2h(e2, e3);
        }
        __syncthreads();

#pragma unroll
        for (int ks = 0; ks < 4; ks++) {
            uint32_t ko = ks * 32;
            uint32_t vko = (uint32_t)(ks * 16 * VSTR) * 2;
            uint32_t ef[4], vh[4][4], vl[4][4];
            ldsm_x4(ef, uE + offEA + ko);
#pragma unroll
            for (int g = 0; g < 4; g++) {
                ldsm_x4t(vh[g], uVh + offVT[g] + vko);
                ldsm_x4t(vl[g], uVl + offVT[g] + vko);
            }
#pragma unroll
            for (int nt = 0; nt < 8; nt++) {
                uint32_t b0 = vh[nt >> 1][(nt & 1) * 2];
                uint32_t b1 = vh[nt >> 1][(nt & 1) * 2 + 1];
                mma16816(o[nt], ef, b0, b1);
                uint32_t c0 = vl[nt >> 1][(nt & 1) * 2];
                uint32_t c1 = vl[nt >> 1][(nt & 1) * 2 + 1];
                mma16816(o[nt], ef, c0, c1);
            }
        }
    }

    sum0 += __shfl_xor_sync(0xffffffffu, sum0, 1);
    sum0 += __shfl_xor_sync(0xffffffffu, sum0, 2);
    sum1 += __shfl_xor_sync(0xffffffffu, sum1, 1);
    sum1 += __shfl_xor_sync(0xffffffffu, sum1, 2);
    __syncthreads();
    if ((lane & 3) == 0) {
        sTmp[wn * 64 + wm * 16 + fr]     = sum0;
        sTmp[wn * 64 + wm * 16 + fr + 8] = sum1;
    }
    __syncthreads();
    if (tid < 64) sFin[tid] = sTmp[tid] + sTmp[64 + tid];
    __syncthreads();

    float inv0 = pwl_inv_f(sFin[wm * 16 + fr]);
    float inv1 = pwl_inv_f(sFin[wm * 16 + fr + 8]);
    size_t row0 = (size_t)(bb * TSEQ + qbase + wm * 16 + fr);
#pragma unroll
    for (int nt = 0; nt < 8; nt++) {
        int col = h * HD + wn * 64 + nt * 8 + (lane & 3) * 2;
        *(uint32_t*)(att + row0 * D_MODEL + col) =
            pack2h(o[nt][0] * inv0, o[nt][1] * inv0);
        *(uint32_t*)(att + (row0 + 8) * D_MODEL + col) =
            pack2h(o[nt][2] * inv1, o[nt][3] * inv1);
    }
}

// ---------------- host launcher ----------------
extern "C" void kernel_launch(void* const* d_in, const int* in_sizes, int n_in,
                              void* d_out, int out_size)
{
    (void)in_sizes; (void)n_in; (void)out_size;
    const float* x      = (const float*)d_in[0];
    const float* ln1w   = (const float*)d_in[1];
    const float* ln1b   = (const float*)d_in[2];
    const float* ln2w   = (const float*)d_in[3];
    const float* ln2b   = (const float*)d_in[4];
    const float* cattw  = (const float*)d_in[5];
    const float* cattb  = (const float*)d_in[6];
    const float* cprojw = (const float*)d_in[7];
    const float* cprojb = (const float*)d_in[8];
    const float* fcw    = (const float*)d_in[9];
    const float* fcb    = (const float*)d_in[10];
    const float* projw  = (const float*)d_in[11];
    const float* projb  = (const float*)d_in[12];
    float* out = (float*)d_out;

    float *x1b, *sbuf;
    cudaGetSymbolAddress((void**)&x1b, g_x1);
    cudaGetSymbolAddress((void**)&sbuf, g_S);

    __half *xn, *qkh, *qkl, *attb, *hb;
    cudaGetSymbolAddress((void**)&xn,   g_xn);
    cudaGetSymbolAddress((void**)&qkh,  g_qkv_h);
    cudaGetSymbolAddress((void**)&qkl,  g_qkv_l);
    cudaGetSymbolAddress((void**)&attb, g_att);
    cudaGetSymbolAddress((void**)&hb,   g_h);

    __half *wqh, *wql, *wph, *wpl, *wfh, *wfl, *wmh, *wml;
    cudaGetSymbolAddress((void**)&wqh, g_wqkv_h);
    cudaGetSymbolAddress((void**)&wql, g_wqkv_l);
    cudaGetSymbolAddress((void**)&wph, g_wproj_h);
    cudaGetSymbolAddress((void**)&wpl, g_wproj_l);
    cudaGetSymbolAddress((void**)&wfh, g_wfc_h);
    cudaGetSymbolAddress((void**)&wfl, g_wfc_l);
    cudaGetSymbolAddress((void**)&wmh, g_wmp_h);
    cudaGetSymbolAddress((void**)&wml, g_wmp_l);

    cudaFuncSetAttribute(attn_mma_kernel, cudaFuncAttributeMaxDynamicSharedMemorySize,
                         ATT_SMEM);
    cudaFuncSetAttribute(gemm_mma_kernel<0>, cudaFuncAttributeMaxDynamicSharedMemorySize,
                         GEMM_SMEM);
    cudaFuncSetAttribute(gemm_mma_kernel<1>, cudaFuncAttributeMaxDynamicSharedMemorySize,
                         GEMM_SMEM);
    cudaFuncSetAttribute(gemm_mma_kernel<2>, cudaFuncAttributeMaxDynamicSharedMemorySize,
                         GEMM_SMEM);

    init_tables_kernel<<<1, 512>>>();

    prep_w_kernel<<<dim3(D3 / 32,      D_MODEL / 32), 256>>>(cattw,  wqh, wql, D_MODEL, D3);
    prep_w_kernel<<<dim3(D_MODEL / 32, D_MODEL / 32), 256>>>(cprojw, wph, wpl, D_MODEL, D_MODEL);
    prep_w_kernel<<<dim3(DFF / 32,     D_MODEL / 32), 256>>>(fcw,    wfh, wfl, D_MODEL, DFF);
    prep_w_kernel<<<dim3(D_MODEL / 32, DFF / 32),     256>>>(projw,  wmh, wml, DFF, D_MODEL);

    // x -> ln1 -> qkv (fp16 hi/lo out)
    ln_kernel<<<NTOK, 256>>>(x, ln1w, ln1b, xn);
    gemm_mma_kernel<0><<<dim3(D3 / 128, NTOK / 128), 256, GEMM_SMEM>>>(
        xn, wqh, wql, cattb, nullptr, nullptr, qkh, qkl, D3, D_MODEL);

    // attention (single fp16 out)
    attn_mma_kernel<<<dim3(TSEQ / 64, NHEAD, NBATCH), 256, ATT_SMEM>>>(
        qkh, qkl, sbuf, attb);

    // x1 = x + att @ c_proj + b   (fp32 out)
    gemm_mma_kernel<2><<<dim3(D_MODEL / 128, NTOK / 128), 256, GEMM_SMEM>>>(
        attb, wph, wpl, cprojb, x, x1b, nullptr, nullptr, D_MODEL, D_MODEL);

    // ln2 -> h = gelu(fc)  (single fp16 out)
    ln_kernel<<<NTOK, 256>>>(x1b, ln2w, ln2b, xn);
    gemm_mma_kernel<1><<<dim3(DFF / 128, NTOK / 128), 256, GEMM_SMEM>>>(
        xn, wfh, wfl, fcb, nullptr, nullptr, hb, nullptr, DFF, D_MODEL);

    // out = x1 + h @ proj + b  (fp32 out)
    gemm_mma_kernel<2><<<dim3(D_MODEL / 128, NTOK / 128), 256, GEMM_SMEM>>>(
        hb, wmh, wml, projb, x1b, out, nullptr, nullptr, D_MODEL, DFF);
}

// round 17
// speedup vs baseline: 2.4195x; 1.4885x over previous
#include <cuda_runtime.h>
#include <cuda_fp16.h>
#include <math.h>
#include <stdint.h>

// ---------------- problem constants ----------------
#define D_MODEL 2048
#define D3      6144
#define DFF     8192
#define TSEQ    1024
#define NBATCH  2
#define NTOK    2048
#define NHEAD   16
#define HD      128

// ---------------- scratch ----------------
static __device__ __align__(128) float g_x1 [NTOK * D_MODEL];
static __device__ __align__(128) float g_S  [NBATCH * NHEAD * TSEQ * TSEQ];

static __device__ __align__(128) __half g_xn  [NTOK * D_MODEL];
static __device__ __align__(128) __half g_qkv [NTOK * D3];
static __device__ __align__(128) __half g_att [NTOK * D_MODEL];
static __device__ __align__(128) __half g_h   [NTOK * DFF];

// pre-transposed single-fp16 weights: layout [N][K]
static __device__ __align__(128) __half g_wqkv [D3  * D_MODEL];
static __device__ __align__(128) __half g_wproj[D_MODEL * D_MODEL];
static __device__ __align__(128) __half g_wfc  [DFF * D_MODEL];
static __device__ __align__(128) __half g_wmp  [D_MODEL * DFF];

// ---------------- PWL tables ----------------
static __device__ float g_gx[512], g_gy[512], g_gs[512];
static __device__ float g_ex[512], g_ey[512], g_es[512];
static __device__ float g_ix[512], g_iy[512], g_is[512];
static __device__ float g_rx[512], g_ry[512], g_rs[512];

__global__ void init_tables_kernel()
{
    int i = threadIdx.x;
    {
        double t = -10.0 + 20.0 * (double)i / 511.0;
        float x = (float)t;
        g_gx[i] = x;
        float inner = x + 0.044715f * x * x * x;
        double y = 0.5 * (double)x * (1.0 + tanh(0.7978845608028653559 * (double)inner));
        g_gy[i] = (float)y;
    }
    {
        double t = -30.0 + 30.0 * (double)i / 511.0;
        float x = (float)t;
        g_ex[i] = x;
        g_ey[i] = (float)exp((double)x);
    }
    {
        double lg = -3.0 + (log10(4096.0) + 3.0) * (double)i / 511.0;
        float x = (float)pow(10.0, lg);
        g_ix[i] = x;
        g_iy[i] = 1.0f / x;
    }
    {
        double lg = -6.0 + 8.0 * (double)i / 511.0;
        float x = (float)pow(10.0, lg);
        g_rx[i] = x;
        g_ry[i] = 1.0f / sqrtf(x);
    }
    __syncthreads();
    if (i < 511) {
        g_gs[i] = (g_gy[i + 1] - g_gy[i]) / (g_gx[i + 1] - g_gx[i]);
        g_es[i] = (g_ey[i + 1] - g_ey[i]) / (g_ex[i + 1] - g_ex[i]);
        g_is[i] = (g_iy[i + 1] - g_iy[i]) / (g_ix[i + 1] - g_ix[i]);
        g_rs[i] = (g_ry[i + 1] - g_ry[i]) / (g_rx[i + 1] - g_rx[i]);
    }
}

// ---------------- interp helpers ----------------
__device__ __forceinline__ float pwl_seg(float x, const float* xp, const float* fp,
                                         const float* sl, int i)
{
    i = min(max(i, 0), 510);
    while (i > 0 && x < xp[i]) --i;
    while (i < 510 && x >= xp[i + 1]) ++i;
    return fp[i] + (x - xp[i]) * sl[i];
}
__device__ __forceinline__ float pwl_gelu_f(float x)
{
    if (x <= g_gx[0])   return g_gy[0];
    if (x >= g_gx[511]) return g_gy[511];
    return pwl_seg(x, g_gx, g_gy, g_gs, (int)((x + 10.0f) * (511.0f / 20.0f)));
}
__device__ __forceinline__ float pwl_exp_f(float x)
{
    if (x <= g_ex[0])   return g_ey[0];
    if (x >= g_ex[511]) return g_ey[511];
    return pwl_seg(x, g_ex, g_ey, g_es, (int)((x + 30.0f) * (511.0f / 30.0f)));
}
__device__ __forceinline__ float pwl_inv_f(float x)
{
    if (x <= g_ix[0])   return g_iy[0];
    if (x >= g_ix[511]) return g_iy[511];
    int i = (int)((log2f(x) + 9.965784284662087f) * 23.263455f);
    return pwl_seg(x, g_ix, g_iy, g_is, i);
}
__device__ __forceinline__ float pwl_rsqrt_f(float x)
{
    if (x <= g_rx[0])   return g_ry[0];
    if (x >= g_rx[511]) return g_ry[511];
    int i = (int)((log2f(x) + 19.931568569324174f) * 19.228312f);
    return pwl_seg(x, g_rx, g_ry, g_rs, i);
}

// ---------------- mma / async helpers ----------------
__device__ __forceinline__ uint32_t smem_u32(const void* p)
{
    uint32_t a;
    asm("{ .reg .u64 t; cvta.to.shared.u64 t, %1; cvt.u32.u64 %0, t; }" : "=r"(a) : "l"(p));
    return a;
}
__device__ __forceinline__ void ldsm_x4(uint32_t* r, uint32_t addr)
{
    asm volatile("ldmatrix.sync.aligned.m8n8.x4.shared.b16 {%0,%1,%2,%3}, [%4];"
                 : "=r"(r[0]), "=r"(r[1]), "=r"(r[2]), "=r"(r[3]) : "r"(addr));
}
__device__ __forceinline__ void ldsm_x4t(uint32_t* r, uint32_t addr)
{
    asm volatile("ldmatrix.sync.aligned.m8n8.x4.trans.shared.b16 {%0,%1,%2,%3}, [%4];"
                 : "=r"(r[0]), "=r"(r[1]), "=r"(r[2]), "=r"(r[3]) : "r"(addr));
}
__device__ __forceinline__ void mma16816(float* c, const uint32_t* a, uint32_t b0, uint32_t b1)
{
    asm volatile(
        "mma.sync.aligned.m16n8k16.row.col.f32.f16.f16.f32 "
        "{%0,%1,%2,%3}, {%4,%5,%6,%7}, {%8,%9}, {%0,%1,%2,%3};"
        : "+f"(c[0]), "+f"(c[1]), "+f"(c[2]), "+f"(c[3])
        : "r"(a[0]), "r"(a[1]), "r"(a[2]), "r"(a[3]), "r"(b0), "r"(b1));
}
__device__ __forceinline__ void cpa16(uint32_t dst, const void* src)
{
    asm volatile("cp.async.cg.shared.global [%0], [%1], 16;" :: "r"(dst), "l"(src));
}
#define CPA_COMMIT() asm volatile("cp.async.commit_group;" ::: "memory")
#define CPA_WAIT1()  asm volatile("cp.async.wait_group 1;" ::: "memory")
#define CPA_WAIT0()  asm volatile("cp.async.wait_group 0;" ::: "memory")

union H2U { __half2 h; uint32_t u; };

__device__ __forceinline__ uint32_t pack2h(float a, float b)
{
    H2U u;
    u.h = __floats2half2_rn(a, b);
    return u.u;
}

// ---------------- weight prep: W[K][N] fp32 -> fp16 [N][K] ----------------
__global__ void __launch_bounds__(256) prep_w_kernel(const float* __restrict__ W,
                                                     __half* __restrict__ hi,
                                                     int K, int N)
{
    __shared__ float ts[32][33];
    int nb = blockIdx.x * 32, kb = blockIdx.y * 32;
    int tx = threadIdx.x & 31, ty = threadIdx.x >> 5;
#pragma unroll
    for (int j = 0; j < 4; j++)
        ts[ty + 8 * j][tx] = W[(size_t)(kb + ty + 8 * j) * N + nb + tx];
    __syncthreads();
#pragma unroll
    for (int j = 0; j < 4; j++) {
        int n_local = ty + 8 * j;
        hi[(size_t)(nb + n_local) * K + kb + tx] = __float2half_rn(ts[tx][n_local]);
    }
}

// ---------------- layernorm: fp32 in -> fp16 out ----------------
__global__ void __launch_bounds__(256) ln_kernel(const float* __restrict__ x,
                                                 const float* __restrict__ w,
                                                 const float* __restrict__ b,
                                                 __half* __restrict__ oh)
{
    __shared__ float red[32];
    int row = blockIdx.x, tid = threadIdx.x;
    const float* xr = x + (size_t)row * D_MODEL;
    int base = tid * 8;
    float4 u0 = *(const float4*)(xr + base);
    float4 u1 = *(const float4*)(xr + base + 4);
    float v[8] = {u0.x, u0.y, u0.z, u0.w, u1.x, u1.y, u1.z, u1.w};

    float s = 0.f;
#pragma unroll
    for (int i = 0; i < 8; i++) s += v[i];
#pragma unroll
    for (int o = 16; o; o >>= 1) s += __shfl_xor_sync(0xffffffffu, s, o);
    int lane = tid & 31, wid = tid >> 5;
    if (lane == 0) red[wid] = s;
    __syncthreads();
    if (tid == 0) {
        float t = 0.f;
#pragma unroll
        for (int i = 0; i < 8; i++) t += red[i];
        red[16] = t * (1.0f / 2048.0f);
    }
    __syncthreads();
    float mu = red[16];

    float sq = 0.f;
#pragma unroll
    for (int i = 0; i < 8; i++) { float d = v[i] - mu; sq += d * d; }
#pragma unroll
    for (int o = 16; o; o >>= 1) sq += __shfl_xor_sync(0xffffffffu, sq, o);
    if (lane == 0) red[wid] = sq;
    __syncthreads();
    if (tid == 0) {
        float t = 0.f;
#pragma unroll
        for (int i = 0; i < 8; i++) t += red[i];
        red[17] = pwl_rsqrt_f(t * (1.0f / 2048.0f) + 1e-5f);
    }
    __syncthreads();
    float inv_std = red[17];

    float4 w0 = *(const float4*)(w + base);
    float4 w1 = *(const float4*)(w + base + 4);
    float4 b0 = *(const float4*)(b + base);
    float4 b1 = *(const float4*)(b + base + 4);
    float wv[8] = {w0.x, w0.y, w0.z, w0.w, w1.x, w1.y, w1.z, w1.w};
    float bv[8] = {b0.x, b0.y, b0.z, b0.w, b1.x, b1.y, b1.z, b1.w};
    float r[8];
#pragma unroll
    for (int i = 0; i < 8; i++) r[i] = (v[i] - mu) * inv_std * wv[i] + bv[i];

    uint32_t hw[4];
#pragma unroll
    for (int i = 0; i < 4; i++) hw[i] = pack2h(r[i * 2], r[i * 2 + 1]);
    size_t o = (size_t)row * D_MODEL + base;
    *(uint4*)(oh + o) = make_uint4(hw[0], hw[1], hw[2], hw[3]);
}

// ---------------- fp16 GEMM, single term, R12 shape, 2-stage cp.async ----------------
#define SSTR 40
#define GTSZ (128 * SSTR * 2)           // 10240 bytes per tile
#define GBUF (2 * GTSZ)                 // A, B
#define GEMM_SMEM (2 * GBUF)            // 40960

template <int EPI>
__global__ void __launch_bounds__(256, 2) gemm_mma_kernel(const __half* __restrict__ A_,
                                                          const __half* __restrict__ B_,
                                                          const float* __restrict__ bias,
                                                          const float* __restrict__ R,
                                                          float* __restrict__ Cf,
                                                          __half* __restrict__ Ch,
                                                          int N, int K)
{
    extern __shared__ char smg[];
    int tid = threadIdx.x;
    int lane = tid & 31, wid = tid >> 5;
    int wm = wid & 3, wn = wid >> 2;
    int bm = blockIdx.y * 128, bn = blockIdx.x * 128;

    uint32_t u0 = smem_u32(smg);

    uint32_t offA[2], offB[4];
#pragma unroll
    for (int mt = 0; mt < 2; mt++) {
        int row = wm * 32 + mt * 16 + (lane & 15);
        int col = (lane >> 4) << 3;
        offA[mt] = (uint32_t)(row * SSTR + col) * 2;
    }
#pragma unroll
    for (int ntp = 0; ntp < 4; ntp++) {
        int n = wn * 64 + ntp * 16 + ((lane >> 4) << 3) + (lane & 7);
        int k = ((lane >> 3) & 1) << 3;
        offB[ntp] = (uint32_t)(n * SSTR + k) * 2;
    }

    float acc[2][8][4];
#pragma unroll
    for (int mt = 0; mt < 2; mt++)
#pragma unroll
        for (int nt = 0; nt < 8; nt++)
#pragma unroll
            for (int q = 0; q < 4; q++) acc[mt][nt][q] = 0.f;

    int lrow = tid >> 1;
    int lsg  = (tid & 1) * 2;
    const char* pA = (const char*)(A_ + (size_t)(bm + lrow) * K);
    const char* pB = (const char*)(B_ + (size_t)(bn + lrow) * K);
    uint32_t drow = (uint32_t)(lrow * SSTR) * 2;

#define LOAD_CHUNK(ch, buf) do {                                            \
    uint32_t sb = u0 + (buf) * GBUF + drow;                                 \
    size_t so = (size_t)(ch) * 64;                                          \
    _Pragma("unroll")                                                       \
    for (int j = 0; j < 2; j++) {                                           \
        uint32_t sg = (uint32_t)(lsg + j) * 16;                             \
        cpa16(sb + 0 * GTSZ + sg, pA + so + sg);                            \
        cpa16(sb + 1 * GTSZ + sg, pB + so + sg);                            \
    } } while (0)

    int nch = K >> 5;
    LOAD_CHUNK(0, 0);
    CPA_COMMIT();

    for (int ch = 0; ch < nch; ch++) {
        int cur = ch & 1;
        if (ch + 1 < nch) {
            LOAD_CHUNK(ch + 1, 1 - cur);
            CPA_COMMIT();
            CPA_WAIT1();
        } else {
            CPA_WAIT0();
        }
        __syncthreads();

        uint32_t uA = u0 + cur * GBUF;
        uint32_t uB = uA + GTSZ;
#pragma unroll
        for (int ks = 0; ks < 2; ks++) {
            uint32_t ko = ks * 32;
            uint32_t ah[2][4], bb[4][4];
#pragma unroll
            for (int mt = 0; mt < 2; mt++)
                ldsm_x4(ah[mt], uA + offA[mt] + ko);
#pragma unroll
            for (int ntp = 0; ntp < 4; ntp++)
                ldsm_x4(bb[ntp], uB + offB[ntp] + ko);
#pragma unroll
            for (int mt = 0; mt < 2; mt++)
#pragma unroll
                for (int nt = 0; nt < 8; nt++) {
                    uint32_t b0 = bb[nt >> 1][(nt & 1) * 2];
                    uint32_t b1 = bb[nt >> 1][(nt & 1) * 2 + 1];
                    mma16816(acc[mt][nt], ah[mt], b0, b1);
                }
        }
        __syncthreads();
    }
#undef LOAD_CHUNK

    // ---- epilogue ----
#pragma unroll
    for (int mt = 0; mt < 2; mt++) {
        int row0 = bm + wm * 32 + mt * 16 + (lane >> 2);
#pragma unroll
        for (int nt = 0; nt < 8; nt++) {
            int col = bn + wn * 64 + nt * 8 + (lane & 3) * 2;
            float2 bv = *(const float2*)(bias + col);
            float v0 = acc[mt][nt][0] + bv.x;
            float v1 = acc[mt][nt][1] + bv.y;
            float v2 = acc[mt][nt][2] + bv.x;
            float v3 = acc[mt][nt][3] + bv.y;
            if (EPI == 1) {
                v0 = pwl_gelu_f(v0); v1 = pwl_gelu_f(v1);
                v2 = pwl_gelu_f(v2); v3 = pwl_gelu_f(v3);
            }
            if (EPI == 2) {
                float2 r0 = *(const float2*)(R + (size_t)row0 * N + col);
                float2 r1 = *(const float2*)(R + (size_t)(row0 + 8) * N + col);
                v0 += r0.x; v1 += r0.y; v2 += r1.x; v3 += r1.y;
                *(float2*)(Cf + (size_t)row0 * N + col)       = make_float2(v0, v1);
                *(float2*)(Cf + (size_t)(row0 + 8) * N + col) = make_float2(v2, v3);
            } else {
                *(uint32_t*)(Ch + (size_t)row0 * N + col)       = pack2h(v0, v1);
                *(uint32_t*)(Ch + (size_t)(row0 + 8) * N + col) = pack2h(v2, v3);
            }
        }
    }
}

// ---------------- attention: single fp16, S-scratch two-pass, trans-ldsm V ----------------
#define QSTR 136
#define VSTR 136
#define ESTR 72
#define A_Q    0
#define A_KV   (A_Q + 64 * QSTR * 2)
#define A_E    (A_KV + 64 * QSTR * 2)
#define A_RED  (A_E + 64 * ESTR * 2)
#define ATT_SMEM (A_RED + 384 * 4)

__global__ void __launch_bounds__(256, 2) attn_mma_kernel(const __half* __restrict__ qkv,
                                                          float* __restrict__ Sbuf,
                                                          __half* __restrict__ att)
{
    extern __shared__ char sma[];
    float* sRed  = (float*)(sma + A_RED);
    float* sTmp  = sRed;
    float* sFin  = sRed + 128;

    int tid = threadIdx.x;
    int lane = tid & 31, wid = tid >> 5;
    int wm = wid & 3, wn = wid >> 2;
    int qt = (int)(gridDim.x - 1 - blockIdx.x);
    int h = blockIdx.y, bb = blockIdx.z;
    int qbase = qt * 64;
    const float scale = 0.08838834764831845f;

    uint32_t u0 = smem_u32(sma);
    uint32_t uQ = u0 + A_Q;
    uint32_t uKV = u0 + A_KV;
    uint32_t uE = u0 + A_E;

    const __half* qp = qkv + (size_t)(bb * TSEQ + qbase) * D3 + h * HD;
    const __half* kp = qkv + (size_t)(bb * TSEQ) * D3 + D_MODEL + h * HD;
    const __half* vp = qkv + (size_t)(bb * TSEQ) * D3 + 2 * D_MODEL + h * HD;

    float* Srow = Sbuf + ((size_t)(bb * NHEAD + h) * TSEQ + qbase) * TSEQ;

    int lrow = tid >> 2, lcb = (tid & 3) * 32;
    uint32_t sQrow = (uint32_t)(lrow * QSTR + lcb) * 2;

#pragma unroll
    for (int j = 0; j < 4; j++)
        *(uint4*)(sma + A_Q + sQrow + j * 16) =
            *(const uint4*)(qp + (size_t)lrow * D3 + lcb + j * 8);

    uint32_t offQA = (uint32_t)((wm * 16 + (lane & 15)) * QSTR + ((lane >> 4) << 3)) * 2;
    uint32_t offKB[2];
#pragma unroll
    for (int ntp = 0; ntp < 2; ntp++) {
        int n = wn * 32 + ntp * 16 + ((lane >> 4) << 3) + (lane & 7);
        offKB[ntp] = (uint32_t)(n * QSTR + (((lane >> 3) & 1) << 3)) * 2;
    }
    uint32_t offEA = (uint32_t)((wm * 16 + (lane & 15)) * ESTR + ((lane >> 4) << 3)) * 2;
    uint32_t offVT[4];
    {
        int vr = (lane & 7) + (((lane >> 3) & 1) << 3);
        int vc = ((lane >> 4) << 3);
#pragma unroll
        for (int g = 0; g < 4; g++)
            offVT[g] = (uint32_t)(vr * VSTR + wn * 64 + g * 16 + vc) * 2;
    }

    int nkt = qt + 1;
    int fr = lane >> 2;
    int grow0 = qbase + wm * 16 + fr;

    // ---- pass 1: S = Q K^T ----
    float mx0 = -INFINITY, mx1 = -INFINITY;
    for (int kb = 0; kb < nkt; kb++) {
        __syncthreads();
#pragma unroll
        for (int j = 0; j < 4; j++)
            *(uint4*)(sma + A_KV + sQrow + j * 16) =
                *(const uint4*)(kp + (size_t)(kb * 64 + lrow) * D3 + lcb + j * 8);
        __syncthreads();

        float s[4][4];
#pragma unroll
        for (int nt = 0; nt < 4; nt++)
#pragma unroll
            for (int q = 0; q < 4; q++) s[nt][q] = 0.f;
#pragma unroll
        for (int ks = 0; ks < 8; ks++) {
            uint32_t ko = ks * 32;
            uint32_t qf[4], kh[2][4];
            ldsm_x4(qf, uQ + offQA + ko);
            ldsm_x4(kh[0], uKV + offKB[0] + ko);
            ldsm_x4(kh[1], uKV + offKB[1] + ko);
#pragma unroll
            for (int nt = 0; nt < 4; nt++) {
                uint32_t b0 = kh[nt >> 1][(nt & 1) * 2];
                uint32_t b1 = kh[nt >> 1][(nt & 1) * 2 + 1];
                mma16816(s[nt], qf, b0, b1);
            }
        }
        bool diag = (kb == qt);
#pragma unroll
        for (int nt = 0; nt < 4; nt++) {
            int colb = wn * 32 + nt * 8 + (lane & 3) * 2;
            int gcol = kb * 64 + colb;
            float v0 = s[nt][0] * scale, v1 = s[nt][1] * scale;
            float v2 = s[nt][2] * scale, v3 = s[nt][3] * scale;
            if (diag) {
                if (gcol     > grow0)     v0 = -INFINITY;
                if (gcol + 1 > grow0)     v1 = -INFINITY;
                if (gcol     > grow0 + 8) v2 = -INFINITY;
                if (gcol + 1 > grow0 + 8) v3 = -INFINITY;
            }
            mx0 = fmaxf(mx0, fmaxf(v0, v1));
            mx1 = fmaxf(mx1, fmaxf(v2, v3));
            int r0 = wm * 16 + fr;
            *(float2*)(Srow + (size_t)r0 * TSEQ + gcol)       = make_float2(v0, v1);
            *(float2*)(Srow + (size_t)(r0 + 8) * TSEQ + gcol) = make_float2(v2, v3);
        }
    }
    mx0 = fmaxf(mx0, __shfl_xor_sync(0xffffffffu, mx0, 1));
    mx0 = fmaxf(mx0, __shfl_xor_sync(0xffffffffu, mx0, 2));
    mx1 = fmaxf(mx1, __shfl_xor_sync(0xffffffffu, mx1, 1));
    mx1 = fmaxf(mx1, __shfl_xor_sync(0xffffffffu, mx1, 2));
    __syncthreads();
    if ((lane & 3) == 0) {
        sTmp[wn * 64 + wm * 16 + fr]     = mx0;
        sTmp[wn * 64 + wm * 16 + fr + 8] = mx1;
    }
    __syncthreads();
    if (tid < 64) sFin[tid] = fmaxf(sTmp[tid], sTmp[64 + tid]);
    __syncthreads();
    float m0 = sFin[wm * 16 + fr];
    float m1 = sFin[wm * 16 + fr + 8];

    // ---- pass 2: E fp16, o += E V ----
    float o[8][4];
#pragma unroll
    for (int nt = 0; nt < 8; nt++)
#pragma unroll
        for (int q = 0; q < 4; q++) o[nt][q] = 0.f;
    float sum0 = 0.f, sum1 = 0.f;

    for (int kb = 0; kb < nkt; kb++) {
        __syncthreads();
#pragma unroll
        for (int j = 0; j < 4; j++)
            *(uint4*)(sma + A_KV + sQrow + j * 16) =
                *(const uint4*)(vp + (size_t)(kb * 64 + lrow) * D3 + lcb + j * 8);
#pragma unroll
        for (int nt = 0; nt < 4; nt++) {
            int colb = wn * 32 + nt * 8 + (lane & 3) * 2;
            int gcol = kb * 64 + colb;
            int r0 = wm * 16 + fr;
            float2 a = *(const float2*)(Srow + (size_t)r0 * TSEQ + gcol);
            float2 b = *(const float2*)(Srow + (size_t)(r0 + 8) * TSEQ + gcol);
            float z0 = fminf(fmaxf(a.x - m0, -30.0f), 0.0f);
            float z1 = fminf(fmaxf(a.y - m0, -30.0f), 0.0f);
            float z2 = fminf(fmaxf(b.x - m1, -30.0f), 0.0f);
            float z3 = fminf(fmaxf(b.y - m1, -30.0f), 0.0f);
            float e0 = pwl_exp_f(z0), e1 = pwl_exp_f(z1);
            float e2 = pwl_exp_f(z2), e3 = pwl_exp_f(z3);
            sum0 += e0 + e1;
            sum1 += e2 + e3;
            *(uint32_t*)(sma + A_E + (r0 * ESTR + colb) * 2)       = pack2h(e0, e1);
            *(uint32_t*)(sma + A_E + ((r0 + 8) * ESTR + colb) * 2) = pack2h(e2, e3);
        }
        __syncthreads();

#pragma unroll
        for (int ks = 0; ks < 4; ks++) {
            uint32_t ko = ks * 32;
            uint32_t vko = (uint32_t)(ks * 16 * VSTR) * 2;
            uint32_t ef[4], vh[4][4];
            ldsm_x4(ef, uE + offEA + ko);
#pragma unroll
            for (int g = 0; g < 4; g++)
                ldsm_x4t(vh[g], uKV + offVT[g] + vko);
#pragma unroll
            for (int nt = 0; nt < 8; nt++) {
                uint32_t b0 = vh[nt >> 1][(nt & 1) * 2];
                uint32_t b1 = vh[nt >> 1][(nt & 1) * 2 + 1];
                mma16816(o[nt], ef, b0, b1);
            }
        }
    }

    sum0 += __shfl_xor_sync(0xffffffffu, sum0, 1);
    sum0 += __shfl_xor_sync(0xffffffffu, sum0, 2);
    sum1 += __shfl_xor_sync(0xffffffffu, sum1, 1);
    sum1 += __shfl_xor_sync(0xffffffffu, sum1, 2);
    __syncthreads();
    if ((lane & 3) == 0) {
        sTmp[wn * 64 + wm * 16 + fr]     = sum0;
        sTmp[wn * 64 + wm * 16 + fr + 8] = sum1;
    }
    __syncthreads();
    if (tid < 64) sFin[tid] = sTmp[tid] + sTmp[64 + tid];
    __syncthreads();

    float inv0 = pwl_inv_f(sFin[wm * 16 + fr]);
    float inv1 = pwl_inv_f(sFin[wm * 16 + fr + 8]);
    size_t row0 = (size_t)(bb * TSEQ + qbase + wm * 16 + fr);
#pragma unroll
    for (int nt = 0; nt < 8; nt++) {
        int col = h * HD + wn * 64 + nt * 8 + (lane & 3) * 2;
        *(uint32_t*)(att + row0 * D_MODEL + col) =
            pack2h(o[nt][0] * inv0, o[nt][1] * inv0);
        *(uint32_t*)(att + (row0 + 8) * D_MODEL + col) =
            pack2h(o[nt][2] * inv1, o[nt][3] * inv1);
    }
}

// ---------------- host launcher ----------------
extern "C" void kernel_launch(void* const* d_in, const int* in_sizes, int n_in,
                              void* d_out, int out_size)
{
    (void)in_sizes; (void)n_in; (void)out_size;
    const float* x      = (const float*)d_in[0];
    const float* ln1w   = (const float*)d_in[1];
    const float* ln1b   = (const float*)d_in[2];
    const float* ln2w   = (const float*)d_in[3];
    const float* ln2b   = (const float*)d_in[4];
    const float* cattw  = (const float*)d_in[5];
    const float* cattb  = (const float*)d_in[6];
    const float* cprojw = (const float*)d_in[7];
    const float* cprojb = (const float*)d_in[8];
    const float* fcw    = (const float*)d_in[9];
    const float* fcb    = (const float*)d_in[10];
    const float* projw  = (const float*)d_in[11];
    const float* projb  = (const float*)d_in[12];
    float* out = (float*)d_out;

    float *x1b, *sbuf;
    cudaGetSymbolAddress((void**)&x1b, g_x1);
    cudaGetSymbolAddress((void**)&sbuf, g_S);

    __half *xn, *qkvb, *attb, *hb;
    cudaGetSymbolAddress((void**)&xn,   g_xn);
    cudaGetSymbolAddress((void**)&qkvb, g_qkv);
    cudaGetSymbolAddress((void**)&attb, g_att);
    cudaGetSymbolAddress((void**)&hb,   g_h);

    __half *wq, *wp, *wf, *wm;
    cudaGetSymbolAddress((void**)&wq, g_wqkv);
    cudaGetSymbolAddress((void**)&wp, g_wproj);
    cudaGetSymbolAddress((void**)&wf, g_wfc);
    cudaGetSymbolAddress((void**)&wm, g_wmp);

    cudaFuncSetAttribute(attn_mma_kernel, cudaFuncAttributeMaxDynamicSharedMemorySize,
                         ATT_SMEM);
    cudaFuncSetAttribute(gemm_mma_kernel<0>, cudaFuncAttributeMaxDynamicSharedMemorySize,
                         GEMM_SMEM);
    cudaFuncSetAttribute(gemm_mma_kernel<1>, cudaFuncAttributeMaxDynamicSharedMemorySize,
                         GEMM_SMEM);
    cudaFuncSetAttribute(gemm_mma_kernel<2>, cudaFuncAttributeMaxDynamicSharedMemorySize,
                         GEMM_SMEM);

    init_tables_kernel<<<1, 512>>>();

    prep_w_kernel<<<dim3(D3 / 32,      D_MODEL / 32), 256>>>(cattw,  wq, D_MODEL, D3);
    prep_w_kernel<<<dim3(D_MODEL / 32, D_MODEL / 32), 256>>>(cprojw, wp, D_MODEL, D_MODEL);
    prep_w_kernel<<<dim3(DFF / 32,     D_MODEL / 32), 256>>>(fcw,    wf, D_MODEL, DFF);
    prep_w_kernel<<<dim3(D_MODEL / 32, DFF / 32),     256>>>(projw,  wm, DFF, D_MODEL);

    // x -> ln1 -> qkv
    ln_kernel<<<NTOK, 256>>>(x, ln1w, ln1b, xn);
    gemm_mma_kernel<0><<<dim3(D3 / 128, NTOK / 128), 256, GEMM_SMEM>>>(
        xn, wq, cattb, nullptr, nullptr, qkvb, D3, D_MODEL);

    // attention
    attn_mma_kernel<<<dim3(TSEQ / 64, NHEAD, NBATCH), 256, ATT_SMEM>>>(
        qkvb, sbuf, attb);

    // x1 = x + att @ c_proj + b   (fp32 out)
    gemm_mma_kernel<2><<<dim3(D_MODEL / 128, NTOK / 128), 256, GEMM_SMEM>>>(
        attb, wp, cprojb, x, x1b, nullptr, D_MODEL, D_MODEL);

    // ln2 -> h = gelu(fc)
    ln_kernel<<<NTOK, 256>>>(x1b, ln2w, ln2b, xn);
    gemm_mma_kernel<1><<<dim3(DFF / 128, NTOK / 128), 256, GEMM_SMEM>>>(
        xn, wf, fcb, nullptr, nullptr, hb, DFF, D_MODEL);

    // out = x1 + h @ proj + b  (fp32 out)
    gemm_mma_kernel<2><<<dim3(D_MODEL / 128, NTOK / 128), 256, GEMM_SMEM>>>(
        hb, wm, projb, x1b, out, nullptr, D_MODEL, DFF);
}